// round 3
// baseline (speedup 1.0000x reference)
#include <cuda_runtime.h>

#define NP 100000
#define ND 50000
#define EMAX 600000

static const size_t TOTAL_BYTES = 256ull * 1024 * 1024;
__device__ __align__(256) unsigned char g_mem[TOTAL_BYTES];

// ---------------------------------------------------------------------------
// f32x2 helpers
// ---------------------------------------------------------------------------

__device__ __forceinline__ unsigned long long pk2dup(float x) {
    unsigned long long r;
    asm("mov.b64 %0, {%1, %1};" : "=l"(r) : "f"(x));
    return r;
}
__device__ __forceinline__ void fma2(unsigned long long& d, unsigned long long a,
                                     unsigned long long b) {
    asm("fma.rn.f32x2 %0, %1, %2, %0;" : "+l"(d) : "l"(a), "l"(b));
}
__device__ __forceinline__ float2 upk2(unsigned long long v) {
    float2 f;
    asm("mov.b64 {%0, %1}, %2;" : "=f"(f.x), "=f"(f.y) : "l"(v));
    return f;
}

// ---------------------------------------------------------------------------
// Fused setup kernels
// ---------------------------------------------------------------------------

__global__ void count4(const int* __restrict__ i0, const int* __restrict__ i1,
                       const int* __restrict__ i2, const int* __restrict__ i3,
                       int* __restrict__ c0, int* __restrict__ c1,
                       int* __restrict__ c2, int* __restrict__ c3,
                       int E0, int E1, int E2, int E3) {
    int e = blockIdx.x * blockDim.x + threadIdx.x;
    int y = blockIdx.y;
    const int* idx = (y == 0) ? i0 : (y == 1) ? i1 : (y == 2) ? i2 : i3;
    int* cnt = (y == 0) ? c0 : (y == 1) ? c1 : (y == 2) ? c2 : c3;
    int E = (y == 0) ? E0 : (y == 1) ? E1 : (y == 2) ? E2 : E3;
    if (e < E) atomicAdd(&cnt[idx[e]], 1);
}

__global__ void inv4(const int* __restrict__ c0, const int* __restrict__ c1,
                     const int* __restrict__ c2, const int* __restrict__ c3,
                     float* __restrict__ v0, float* __restrict__ v1,
                     float* __restrict__ v2, float* __restrict__ v3,
                     int n0, int n1, int n2, int n3) {
    int i = blockIdx.x * blockDim.x + threadIdx.x;
    int y = blockIdx.y;
    const int* cnt = (y == 0) ? c0 : (y == 1) ? c1 : (y == 2) ? c2 : c3;
    float* inv = (y == 0) ? v0 : (y == 1) ? v1 : (y == 2) ? v2 : v3;
    int n = (y == 0) ? n0 : (y == 1) ? n1 : (y == 2) ? n2 : n3;
    if (i < n) {
        int c = cnt[i];
        if (c < 1) c = 1;
        inv[i] = rsqrtf((float)c);
    }
}

// 2 blocks: block 0 scans (cA,n A)->rpA, block 1 scans (cB,nB)->rpB.
__global__ void scan2(const int* __restrict__ cA, int* __restrict__ rpA, int nA,
                      const int* __restrict__ cB, int* __restrict__ rpB, int nB) {
    const int* cnt = blockIdx.x ? cB : cA;
    int* rowptr = blockIdx.x ? rpB : rpA;
    int n = blockIdx.x ? nB : nA;

    __shared__ int warp_sums[32];
    __shared__ int carry_s;
    int lane = threadIdx.x & 31;
    int warp = threadIdx.x >> 5;
    if (threadIdx.x == 0) { carry_s = 0; rowptr[0] = 0; }
    __syncthreads();
    for (int base = 0; base < n; base += 1024) {
        int i = base + (int)threadIdx.x;
        int v = (i < n) ? cnt[i] : 0;
        int x = v;
        #pragma unroll
        for (int off = 1; off < 32; off <<= 1) {
            int y = __shfl_up_sync(0xffffffffu, x, off);
            if (lane >= off) x += y;
        }
        if (lane == 31) warp_sums[warp] = x;
        __syncthreads();
        if (warp == 0) {
            int s = warp_sums[lane];
            #pragma unroll
            for (int off = 1; off < 32; off <<= 1) {
                int y = __shfl_up_sync(0xffffffffu, s, off);
                if (lane >= off) s += y;
            }
            warp_sums[lane] = s;
        }
        __syncthreads();
        int incl = carry_s + (warp ? warp_sums[warp - 1] : 0) + x;
        if (i < n) rowptr[i + 1] = incl;
        __syncthreads();
        if (threadIdx.x == 1023) carry_s = incl;
        __syncthreads();
    }
}

__global__ void fill2(const int* __restrict__ sA, const int* __restrict__ dA,
                      const int* __restrict__ rpA, int* __restrict__ curA,
                      int* __restrict__ colA, int EA,
                      const int* __restrict__ sB, const int* __restrict__ dB,
                      const int* __restrict__ rpB, int* __restrict__ curB,
                      int* __restrict__ colB, int EB) {
    int e = blockIdx.x * blockDim.x + threadIdx.x;
    const int* src = blockIdx.y ? sB : sA;
    const int* dst = blockIdx.y ? dB : dA;
    const int* rowptr = blockIdx.y ? rpB : rpA;
    int* cursor = blockIdx.y ? curB : curA;
    int* col = blockIdx.y ? colB : colA;
    int E = blockIdx.y ? EB : EA;
    if (e >= E) return;
    int d = dst[e];
    int pos = atomicAdd(&cursor[d], 1);
    col[rowptr[d] + pos] = src[e];
}

// ---------------------------------------------------------------------------
// Device-side roles
// ---------------------------------------------------------------------------

template <bool SRC_SCALE, bool BIAS_RELU>
__device__ __forceinline__ void agg_block(
    int agg_id, const float* __restrict__ x, const int* __restrict__ rowptr,
    const int* __restrict__ col, const float* __restrict__ inv_src,
    const float* __restrict__ inv_dst, const float* __restrict__ bias,
    float* __restrict__ out, int n) {
    int r = agg_id * 8 + (int)(threadIdx.x >> 5);
    if (r >= n) return;
    int lane = threadIdx.x & 31;
    int s = rowptr[r], e = rowptr[r + 1];
    float a0 = 0.f, a1 = 0.f, a2 = 0.f, a3 = 0.f;
    int i = s;
    for (; i + 4 <= e; i += 4) {
        int c0 = col[i], c1 = col[i + 1], c2 = col[i + 2], c3 = col[i + 3];
        float4 v0 = *reinterpret_cast<const float4*>(x + c0 * 128 + lane * 4);
        float4 v1 = *reinterpret_cast<const float4*>(x + c1 * 128 + lane * 4);
        float4 v2 = *reinterpret_cast<const float4*>(x + c2 * 128 + lane * 4);
        float4 v3 = *reinterpret_cast<const float4*>(x + c3 * 128 + lane * 4);
        if (SRC_SCALE) {
            float s0 = inv_src[c0], s1 = inv_src[c1], s2 = inv_src[c2], s3 = inv_src[c3];
            a0 += v0.x * s0 + v1.x * s1 + v2.x * s2 + v3.x * s3;
            a1 += v0.y * s0 + v1.y * s1 + v2.y * s2 + v3.y * s3;
            a2 += v0.z * s0 + v1.z * s1 + v2.z * s2 + v3.z * s3;
            a3 += v0.w * s0 + v1.w * s1 + v2.w * s2 + v3.w * s3;
        } else {
            a0 += (v0.x + v1.x) + (v2.x + v3.x);
            a1 += (v0.y + v1.y) + (v2.y + v3.y);
            a2 += (v0.z + v1.z) + (v2.z + v3.z);
            a3 += (v0.w + v1.w) + (v2.w + v3.w);
        }
    }
    for (; i < e; i++) {
        int c0 = col[i];
        float4 v0 = *reinterpret_cast<const float4*>(x + c0 * 128 + lane * 4);
        float s0 = SRC_SCALE ? inv_src[c0] : 1.0f;
        a0 += v0.x * s0; a1 += v0.y * s0; a2 += v0.z * s0; a3 += v0.w * s0;
    }
    float sc = inv_dst[r];
    a0 *= sc; a1 *= sc; a2 *= sc; a3 *= sc;
    if (BIAS_RELU) {
        float4 bv = *reinterpret_cast<const float4*>(bias + lane * 4);
        a0 = fmaxf(a0 + bv.x, 0.f);
        a1 = fmaxf(a1 + bv.y, 0.f);
        a2 = fmaxf(a2 + bv.z, 0.f);
        a3 = fmaxf(a3 + bv.w, 0.f);
    }
    float4 o; o.x = a0; o.y = a1; o.z = a2; o.w = a3;
    *reinterpret_cast<float4*>(out + r * 128 + lane * 4) = o;
}

// GEMM role: BM=BN=128, BK=8, 8x8 microtile, FFMA2 with pack-free W operands.
template <bool ROW_SCALE, bool BIAS_RELU>
__device__ __forceinline__ void gemm_block(
    int gemm_id, float (&As)[8][128], float (&Ws)[8][128],
    const float* __restrict__ A, const float* __restrict__ W,
    const float* __restrict__ rscale, const float* __restrict__ bias,
    float* __restrict__ out, int M) {
    int tid = threadIdx.x;
    int block_row = gemm_id * 128;
    int tm = (tid >> 4) << 3;
    int tn = (tid & 15) << 3;

    unsigned long long acc[8][4];
    #pragma unroll
    for (int i = 0; i < 8; i++)
        #pragma unroll
        for (int j = 0; j < 4; j++) acc[i][j] = 0ull;

    int ar = tid >> 1;
    int ap = (tid & 1) * 4;
    int wr = tid >> 5;
    int wc = (tid & 31) * 4;
    int gr_load = block_row + ar;

    float rs = 1.0f;
    if (ROW_SCALE && gr_load < M) rs = rscale[gr_load];

    for (int k0 = 0; k0 < 128; k0 += 8) {
        float4 av = make_float4(0.f, 0.f, 0.f, 0.f);
        if (gr_load < M)
            av = *reinterpret_cast<const float4*>(A + gr_load * 128 + k0 + ap);
        if (ROW_SCALE) { av.x *= rs; av.y *= rs; av.z *= rs; av.w *= rs; }
        As[ap + 0][ar] = av.x;
        As[ap + 1][ar] = av.y;
        As[ap + 2][ar] = av.z;
        As[ap + 3][ar] = av.w;
        *reinterpret_cast<float4*>(&Ws[wr][wc]) =
            *reinterpret_cast<const float4*>(W + (k0 + wr) * 128 + wc);
        __syncthreads();
        #pragma unroll
        for (int kk = 0; kk < 8; kk++) {
            // W n-pairs read directly as packed u64 — no MOV packing.
            ulonglong2 wA = *reinterpret_cast<ulonglong2*>(&Ws[kk][tn]);
            ulonglong2 wB = *reinterpret_cast<ulonglong2*>(&Ws[kk][tn + 4]);
            float4 a0 = *reinterpret_cast<float4*>(&As[kk][tm]);
            float4 a1 = *reinterpret_cast<float4*>(&As[kk][tm + 4]);
            float af[8] = {a0.x, a0.y, a0.z, a0.w, a1.x, a1.y, a1.z, a1.w};
            #pragma unroll
            for (int i = 0; i < 8; i++) {
                unsigned long long ai = pk2dup(af[i]);
                fma2(acc[i][0], ai, wA.x);
                fma2(acc[i][1], ai, wA.y);
                fma2(acc[i][2], ai, wB.x);
                fma2(acc[i][3], ai, wB.y);
            }
        }
        __syncthreads();
    }

    #pragma unroll
    for (int i = 0; i < 8; i++) {
        int gr = block_row + tm + i;
        if (gr >= M) continue;
        #pragma unroll
        for (int j = 0; j < 2; j++) {
            float2 p0 = upk2(acc[i][j * 2 + 0]);
            float2 p1 = upk2(acc[i][j * 2 + 1]);
            float4 v = make_float4(p0.x, p0.y, p1.x, p1.y);
            if (BIAS_RELU) {
                v.x = fmaxf(v.x + bias[tn + j * 4 + 0], 0.f);
                v.y = fmaxf(v.y + bias[tn + j * 4 + 1], 0.f);
                v.z = fmaxf(v.z + bias[tn + j * 4 + 2], 0.f);
                v.w = fmaxf(v.w + bias[tn + j * 4 + 3], 0.f);
            }
            *reinterpret_cast<float4*>(out + gr * 128 + tn + j * 4) = v;
        }
    }
}

// ---------------------------------------------------------------------------
// Fused layer kernels: gemm blocks strided 1-in-STRIDE through the grid so
// every wave mixes FMA-bound (gemm) and L2-bound (agg) blocks.
// grid.x = GEMM_GRID * STRIDE.  gemm: r % STRIDE == 0.  agg_id = r - r/STRIDE - 1.
// ---------------------------------------------------------------------------

template <bool G_RS, bool G_BR, bool A_SS, bool A_BR>
__global__ void __launch_bounds__(256) fused_layer(
    // gemm half
    const float* __restrict__ gA, const float* __restrict__ gW,
    const float* __restrict__ g_rscale, const float* __restrict__ g_bias,
    float* __restrict__ g_out, int gM, int stride,
    // agg half
    const float* __restrict__ aX, const int* __restrict__ rowptr,
    const int* __restrict__ col, const float* __restrict__ a_inv_src,
    const float* __restrict__ a_inv_dst, const float* __restrict__ a_bias,
    float* __restrict__ a_out, int aN) {
    __shared__ __align__(16) float As[8][128];
    __shared__ __align__(16) float Ws[8][128];
    int r = blockIdx.x;
    int q = r / stride;
    if (r - q * stride == 0) {
        gemm_block<G_RS, G_BR>(q, As, Ws, gA, gW, g_rscale, g_bias, g_out, gM);
    } else {
        agg_block<A_SS, A_BR>(r - q - 1, aX, rowptr, col, a_inv_src, a_inv_dst,
                              a_bias, a_out, aN);
    }
}

// ---------------------------------------------------------------------------
// Launch
// ---------------------------------------------------------------------------

extern "C" void kernel_launch(void* const* d_in, const int* in_sizes, int n_in,
                              void* d_out, int out_size) {
    const float* h_p   = (const float*)d_in[0];
    const float* h_d   = (const float*)d_in[1];
    const int* pd_src  = (const int*)d_in[2];
    const int* pd_dst  = (const int*)d_in[3];
    const int* dp_src  = (const int*)d_in[4];
    const int* dp_dst  = (const int*)d_in[5];
    const float* W1_pd = (const float*)d_in[6];
    const float* b1_pd = (const float*)d_in[7];
    const float* W1_dp = (const float*)d_in[8];
    const float* b1_dp = (const float*)d_in[9];
    const float* W2_pd = (const float*)d_in[10];
    const float* b2_pd = (const float*)d_in[11];
    const float* W2_dp = (const float*)d_in[12];
    const float* b2_dp = (const float*)d_in[13];
    const float* W3_pd = (const float*)d_in[14];
    const float* b3_pd = (const float*)d_in[15];
    const float* W3_dp = (const float*)d_in[16];
    const float* b3_dp = (const float*)d_in[17];

    int E  = in_sizes[2];
    int E2 = in_sizes[4];

    void* base = nullptr;
    cudaGetSymbolAddress(&base, g_mem);
    unsigned char* p = (unsigned char*)base;
    auto bump = [&](size_t bytes) -> void* {
        void* r = (void*)p;
        p += (bytes + 255) & ~(size_t)255;
        return r;
    };

    float* inv_p_out = (float*)bump((size_t)NP * 4);
    float* inv_d_in  = (float*)bump((size_t)ND * 4);
    float* inv_d_out = (float*)bump((size_t)ND * 4);
    float* inv_p_in  = (float*)bump((size_t)NP * 4);
    int* cnt_p_out   = (int*)bump((size_t)NP * 4);
    int* cnt_d_in    = (int*)bump((size_t)ND * 4);
    int* cnt_d_out   = (int*)bump((size_t)ND * 4);
    int* cnt_p_in    = (int*)bump((size_t)NP * 4);
    int* cur_pd      = (int*)bump((size_t)ND * 4);
    int* cur_dp      = (int*)bump((size_t)NP * 4);
    int* rp_pd       = (int*)bump((size_t)(ND + 1) * 4);
    int* rp_dp       = (int*)bump((size_t)(NP + 1) * 4);
    int* col_pd      = (int*)bump((size_t)EMAX * 4);
    int* col_dp      = (int*)bump((size_t)EMAX * 4);
    float* hd1       = (float*)bump((size_t)ND * 128 * 4);
    float* hd2       = (float*)bump((size_t)ND * 128 * 4);
    float* hp1       = (float*)bump((size_t)NP * 128 * 4);
    float* hp2       = (float*)bump((size_t)NP * 128 * 4);
    float* scr_pd    = (float*)bump((size_t)ND * 128 * 4);  // agg_pd output
    float* scr_dp    = (float*)bump((size_t)ND * 128 * 4);  // gemm_dp output

    float* out_p = (float*)d_out;
    float* out_d = out_p + (size_t)NP * 128;

    // zero counters + cursors (memset nodes, not kernel launches)
    cudaMemsetAsync(cnt_p_out, 0, (size_t)NP * 4);
    cudaMemsetAsync(cnt_d_in, 0, (size_t)ND * 4);
    cudaMemsetAsync(cnt_d_out, 0, (size_t)ND * 4);
    cudaMemsetAsync(cnt_p_in, 0, (size_t)NP * 4);
    cudaMemsetAsync(cur_pd, 0, (size_t)ND * 4);
    cudaMemsetAsync(cur_dp, 0, (size_t)NP * 4);

    int Emax = (E > E2) ? E : E2;
    dim3 cg((Emax + 255) / 256, 4);
    count4<<<cg, 256>>>(pd_src, pd_dst, dp_src, dp_dst,
                        cnt_p_out, cnt_d_in, cnt_d_out, cnt_p_in, E, E, E2, E2);

    dim3 ig((NP + 255) / 256, 4);
    inv4<<<ig, 256>>>(cnt_p_out, cnt_d_in, cnt_d_out, cnt_p_in,
                      inv_p_out, inv_d_in, inv_d_out, inv_p_in, NP, ND, ND, NP);

    scan2<<<2, 1024>>>(cnt_d_in, rp_pd, ND, cnt_p_in, rp_dp, NP);

    dim3 fg((Emax + 255) / 256, 2);
    fill2<<<fg, 256>>>(pd_src, pd_dst, rp_pd, cur_pd, col_pd, E,
                       dp_src, dp_dst, rp_dp, cur_dp, col_dp, E2);

    // layer grids
    const int G = (ND + 127) / 128;           // 391 gemm blocks
    const int AA = (ND + 7) / 8;              // agg_pd blocks (6250)
    const int AB = (NP + 7) / 8;              // agg_dp blocks (12500)
    const int strideA = (G + AA + G - 1) / G; // 17
    const int strideB = (G + AB + G - 1) / G; // 33
    const int gridA = G * strideA;
    const int gridB = G * strideB;

    // Kernel A: agg_pd(x_p -> scr_pd) + gemm_dp(x_d * inv_d_out @ W -> scr_dp)
    // Kernel B: gemm_pd(scr_pd @ W + b, relu -> o_d) + agg_dp(scr_dp -> o_p, +b relu)
    auto layer = [&](const float* x_p, const float* x_d,
                     const float* Wpd, const float* bpd,
                     const float* Wdp, const float* bdp,
                     float* o_d, float* o_p) {
        fused_layer<true, false, true, false><<<gridA, 256>>>(
            x_d, Wdp, inv_d_out, nullptr, scr_dp, ND, strideA,
            x_p, rp_pd, col_pd, inv_p_out, inv_d_in, nullptr, scr_pd, ND);
        fused_layer<false, true, false, true><<<gridB, 256>>>(
            scr_pd, Wpd, nullptr, bpd, o_d, ND, strideB,
            scr_dp, rp_dp, col_dp, nullptr, inv_p_in, bdp, o_p, NP);
    };

    layer(h_p, h_d, W1_pd, b1_pd, W1_dp, b1_dp, hd1, hp1);
    layer(hp1, hd1, W2_pd, b2_pd, W2_dp, b2_dp, hd2, hp2);
    layer(hp2, hd2, W3_pd, b3_pd, W3_dp, b3_dp, out_d, out_p);
}

// round 4
// speedup vs baseline: 1.5793x; 1.5793x over previous
#include <cuda_runtime.h>

#define NP 100000
#define ND 50000
#define EMAX 600000

static const size_t TOTAL_BYTES = 256ull * 1024 * 1024;
__device__ __align__(256) unsigned char g_mem[TOTAL_BYTES];

// ---------------------------------------------------------------------------
// f32x2 helpers
// ---------------------------------------------------------------------------

__device__ __forceinline__ unsigned long long pk2dup(float x) {
    unsigned long long r;
    asm("mov.b64 %0, {%1, %1};" : "=l"(r) : "f"(x));
    return r;
}
__device__ __forceinline__ void fma2(unsigned long long& d, unsigned long long a,
                                     unsigned long long b) {
    asm("fma.rn.f32x2 %0, %1, %2, %0;" : "+l"(d) : "l"(a), "l"(b));
}
__device__ __forceinline__ float2 upk2(unsigned long long v) {
    float2 f;
    asm("mov.b64 {%0, %1}, %2;" : "=f"(f.x), "=f"(f.y) : "l"(v));
    return f;
}

// ---------------------------------------------------------------------------
// Fused setup kernels
// ---------------------------------------------------------------------------

__global__ void count4(const int* __restrict__ i0, const int* __restrict__ i1,
                       const int* __restrict__ i2, const int* __restrict__ i3,
                       int* __restrict__ c0, int* __restrict__ c1,
                       int* __restrict__ c2, int* __restrict__ c3,
                       int E0, int E1, int E2, int E3) {
    int e = blockIdx.x * blockDim.x + threadIdx.x;
    int y = blockIdx.y;
    const int* idx = (y == 0) ? i0 : (y == 1) ? i1 : (y == 2) ? i2 : i3;
    int* cnt = (y == 0) ? c0 : (y == 1) ? c1 : (y == 2) ? c2 : c3;
    int E = (y == 0) ? E0 : (y == 1) ? E1 : (y == 2) ? E2 : E3;
    if (e < E) atomicAdd(&cnt[idx[e]], 1);
}

__global__ void inv4(const int* __restrict__ c0, const int* __restrict__ c1,
                     const int* __restrict__ c2, const int* __restrict__ c3,
                     float* __restrict__ v0, float* __restrict__ v1,
                     float* __restrict__ v2, float* __restrict__ v3,
                     int n0, int n1, int n2, int n3) {
    int i = blockIdx.x * blockDim.x + threadIdx.x;
    int y = blockIdx.y;
    const int* cnt = (y == 0) ? c0 : (y == 1) ? c1 : (y == 2) ? c2 : c3;
    float* inv = (y == 0) ? v0 : (y == 1) ? v1 : (y == 2) ? v2 : v3;
    int n = (y == 0) ? n0 : (y == 1) ? n1 : (y == 2) ? n2 : n3;
    if (i < n) {
        int c = cnt[i];
        if (c < 1) c = 1;
        inv[i] = rsqrtf((float)c);
    }
}

__global__ void scan2(const int* __restrict__ cA, int* __restrict__ rpA, int nA,
                      const int* __restrict__ cB, int* __restrict__ rpB, int nB) {
    const int* cnt = blockIdx.x ? cB : cA;
    int* rowptr = blockIdx.x ? rpB : rpA;
    int n = blockIdx.x ? nB : nA;

    __shared__ int warp_sums[32];
    __shared__ int carry_s;
    int lane = threadIdx.x & 31;
    int warp = threadIdx.x >> 5;
    if (threadIdx.x == 0) { carry_s = 0; rowptr[0] = 0; }
    __syncthreads();
    for (int base = 0; base < n; base += 1024) {
        int i = base + (int)threadIdx.x;
        int v = (i < n) ? cnt[i] : 0;
        int x = v;
        #pragma unroll
        for (int off = 1; off < 32; off <<= 1) {
            int y = __shfl_up_sync(0xffffffffu, x, off);
            if (lane >= off) x += y;
        }
        if (lane == 31) warp_sums[warp] = x;
        __syncthreads();
        if (warp == 0) {
            int s = warp_sums[lane];
            #pragma unroll
            for (int off = 1; off < 32; off <<= 1) {
                int y = __shfl_up_sync(0xffffffffu, s, off);
                if (lane >= off) s += y;
            }
            warp_sums[lane] = s;
        }
        __syncthreads();
        int incl = carry_s + (warp ? warp_sums[warp - 1] : 0) + x;
        if (i < n) rowptr[i + 1] = incl;
        __syncthreads();
        if (threadIdx.x == 1023) carry_s = incl;
        __syncthreads();
    }
}

__global__ void fill2(const int* __restrict__ sA, const int* __restrict__ dA,
                      const int* __restrict__ rpA, int* __restrict__ curA,
                      int* __restrict__ colA, int EA,
                      const int* __restrict__ sB, const int* __restrict__ dB,
                      const int* __restrict__ rpB, int* __restrict__ curB,
                      int* __restrict__ colB, int EB) {
    int e = blockIdx.x * blockDim.x + threadIdx.x;
    const int* src = blockIdx.y ? sB : sA;
    const int* dst = blockIdx.y ? dB : dA;
    const int* rowptr = blockIdx.y ? rpB : rpA;
    int* cursor = blockIdx.y ? curB : curA;
    int* col = blockIdx.y ? colB : colA;
    int E = blockIdx.y ? EB : EA;
    if (e >= E) return;
    int d = dst[e];
    int pos = atomicAdd(&cursor[d], 1);
    col[rowptr[d] + pos] = src[e];
}

// ---------------------------------------------------------------------------
// Aggregation kernel (standalone — low regs, high occupancy, MLP-driven)
// ---------------------------------------------------------------------------

template <bool SRC_SCALE, bool BIAS_RELU>
__global__ void __launch_bounds__(256) agg_kernel(
    const float* __restrict__ x, const int* __restrict__ rowptr,
    const int* __restrict__ col, const float* __restrict__ inv_src,
    const float* __restrict__ inv_dst, const float* __restrict__ bias,
    float* __restrict__ out, int n) {
    int r = blockIdx.x * 8 + (int)(threadIdx.x >> 5);
    if (r >= n) return;
    int lane = threadIdx.x & 31;
    int s = rowptr[r], e = rowptr[r + 1];
    float a0 = 0.f, a1 = 0.f, a2 = 0.f, a3 = 0.f;
    int i = s;
    for (; i + 4 <= e; i += 4) {
        int c0 = col[i], c1 = col[i + 1], c2 = col[i + 2], c3 = col[i + 3];
        float4 v0 = *reinterpret_cast<const float4*>(x + c0 * 128 + lane * 4);
        float4 v1 = *reinterpret_cast<const float4*>(x + c1 * 128 + lane * 4);
        float4 v2 = *reinterpret_cast<const float4*>(x + c2 * 128 + lane * 4);
        float4 v3 = *reinterpret_cast<const float4*>(x + c3 * 128 + lane * 4);
        if (SRC_SCALE) {
            float s0 = inv_src[c0], s1 = inv_src[c1], s2 = inv_src[c2], s3 = inv_src[c3];
            a0 += v0.x * s0 + v1.x * s1 + v2.x * s2 + v3.x * s3;
            a1 += v0.y * s0 + v1.y * s1 + v2.y * s2 + v3.y * s3;
            a2 += v0.z * s0 + v1.z * s1 + v2.z * s2 + v3.z * s3;
            a3 += v0.w * s0 + v1.w * s1 + v2.w * s2 + v3.w * s3;
        } else {
            a0 += (v0.x + v1.x) + (v2.x + v3.x);
            a1 += (v0.y + v1.y) + (v2.y + v3.y);
            a2 += (v0.z + v1.z) + (v2.z + v3.z);
            a3 += (v0.w + v1.w) + (v2.w + v3.w);
        }
    }
    for (; i < e; i++) {
        int c0 = col[i];
        float4 v0 = *reinterpret_cast<const float4*>(x + c0 * 128 + lane * 4);
        float s0 = SRC_SCALE ? inv_src[c0] : 1.0f;
        a0 += v0.x * s0; a1 += v0.y * s0; a2 += v0.z * s0; a3 += v0.w * s0;
    }
    float sc = inv_dst[r];
    a0 *= sc; a1 *= sc; a2 *= sc; a3 *= sc;
    if (BIAS_RELU) {
        float4 bv = *reinterpret_cast<const float4*>(bias + lane * 4);
        a0 = fmaxf(a0 + bv.x, 0.f);
        a1 = fmaxf(a1 + bv.y, 0.f);
        a2 = fmaxf(a2 + bv.z, 0.f);
        a3 = fmaxf(a3 + bv.w, 0.f);
    }
    float4 o; o.x = a0; o.y = a1; o.z = a2; o.w = a3;
    *reinterpret_cast<float4*>(out + r * 128 + lane * 4) = o;
}

// ---------------------------------------------------------------------------
// GEMM kernel (standalone): BM=BN=128, BK=8, 8x8 microtile,
// FFMA2 with pack-free W operands (W n-pairs loaded as packed u64 from shared).
// ---------------------------------------------------------------------------

template <bool ROW_SCALE, bool BIAS_RELU>
__global__ void __launch_bounds__(256) gemm128(
    const float* __restrict__ A, const float* __restrict__ W,
    const float* __restrict__ rscale, const float* __restrict__ bias,
    float* __restrict__ out, int M) {
    __shared__ __align__(16) float As[8][128];
    __shared__ __align__(16) float Ws[8][128];
    int tid = threadIdx.x;
    int block_row = blockIdx.x * 128;
    int tm = (tid >> 4) << 3;
    int tn = (tid & 15) << 3;

    unsigned long long acc[8][4];
    #pragma unroll
    for (int i = 0; i < 8; i++)
        #pragma unroll
        for (int j = 0; j < 4; j++) acc[i][j] = 0ull;

    int ar = tid >> 1;
    int ap = (tid & 1) * 4;
    int wr = tid >> 5;
    int wc = (tid & 31) * 4;
    int gr_load = block_row + ar;

    float rs = 1.0f;
    if (ROW_SCALE && gr_load < M) rs = rscale[gr_load];

    for (int k0 = 0; k0 < 128; k0 += 8) {
        float4 av = make_float4(0.f, 0.f, 0.f, 0.f);
        if (gr_load < M)
            av = *reinterpret_cast<const float4*>(A + gr_load * 128 + k0 + ap);
        if (ROW_SCALE) { av.x *= rs; av.y *= rs; av.z *= rs; av.w *= rs; }
        As[ap + 0][ar] = av.x;
        As[ap + 1][ar] = av.y;
        As[ap + 2][ar] = av.z;
        As[ap + 3][ar] = av.w;
        *reinterpret_cast<float4*>(&Ws[wr][wc]) =
            *reinterpret_cast<const float4*>(W + (k0 + wr) * 128 + wc);
        __syncthreads();
        #pragma unroll
        for (int kk = 0; kk < 8; kk++) {
            ulonglong2 wA = *reinterpret_cast<ulonglong2*>(&Ws[kk][tn]);
            ulonglong2 wB = *reinterpret_cast<ulonglong2*>(&Ws[kk][tn + 4]);
            float4 a0 = *reinterpret_cast<float4*>(&As[kk][tm]);
            float4 a1 = *reinterpret_cast<float4*>(&As[kk][tm + 4]);
            float af[8] = {a0.x, a0.y, a0.z, a0.w, a1.x, a1.y, a1.z, a1.w};
            #pragma unroll
            for (int i = 0; i < 8; i++) {
                unsigned long long ai = pk2dup(af[i]);
                fma2(acc[i][0], ai, wA.x);
                fma2(acc[i][1], ai, wA.y);
                fma2(acc[i][2], ai, wB.x);
                fma2(acc[i][3], ai, wB.y);
            }
        }
        __syncthreads();
    }

    #pragma unroll
    for (int i = 0; i < 8; i++) {
        int gr = block_row + tm + i;
        if (gr >= M) continue;
        #pragma unroll
        for (int j = 0; j < 2; j++) {
            float2 p0 = upk2(acc[i][j * 2 + 0]);
            float2 p1 = upk2(acc[i][j * 2 + 1]);
            float4 v = make_float4(p0.x, p0.y, p1.x, p1.y);
            if (BIAS_RELU) {
                v.x = fmaxf(v.x + bias[tn + j * 4 + 0], 0.f);
                v.y = fmaxf(v.y + bias[tn + j * 4 + 1], 0.f);
                v.z = fmaxf(v.z + bias[tn + j * 4 + 2], 0.f);
                v.w = fmaxf(v.w + bias[tn + j * 4 + 3], 0.f);
            }
            *reinterpret_cast<float4*>(out + gr * 128 + tn + j * 4) = v;
        }
    }
}

// ---------------------------------------------------------------------------
// Launch
// ---------------------------------------------------------------------------

extern "C" void kernel_launch(void* const* d_in, const int* in_sizes, int n_in,
                              void* d_out, int out_size) {
    const float* h_p   = (const float*)d_in[0];
    const float* h_d   = (const float*)d_in[1];
    const int* pd_src  = (const int*)d_in[2];
    const int* pd_dst  = (const int*)d_in[3];
    const int* dp_src  = (const int*)d_in[4];
    const int* dp_dst  = (const int*)d_in[5];
    const float* W1_pd = (const float*)d_in[6];
    const float* b1_pd = (const float*)d_in[7];
    const float* W1_dp = (const float*)d_in[8];
    const float* b1_dp = (const float*)d_in[9];
    const float* W2_pd = (const float*)d_in[10];
    const float* b2_pd = (const float*)d_in[11];
    const float* W2_dp = (const float*)d_in[12];
    const float* b2_dp = (const float*)d_in[13];
    const float* W3_pd = (const float*)d_in[14];
    const float* b3_pd = (const float*)d_in[15];
    const float* W3_dp = (const float*)d_in[16];
    const float* b3_dp = (const float*)d_in[17];

    int E  = in_sizes[2];
    int E2 = in_sizes[4];

    void* base = nullptr;
    cudaGetSymbolAddress(&base, g_mem);
    unsigned char* p = (unsigned char*)base;
    auto bump = [&](size_t bytes) -> void* {
        void* r = (void*)p;
        p += (bytes + 255) & ~(size_t)255;
        return r;
    };

    float* inv_p_out = (float*)bump((size_t)NP * 4);
    float* inv_d_in  = (float*)bump((size_t)ND * 4);
    float* inv_d_out = (float*)bump((size_t)ND * 4);
    float* inv_p_in  = (float*)bump((size_t)NP * 4);
    int* cnt_p_out   = (int*)bump((size_t)NP * 4);
    int* cnt_d_in    = (int*)bump((size_t)ND * 4);
    int* cnt_d_out   = (int*)bump((size_t)ND * 4);
    int* cnt_p_in    = (int*)bump((size_t)NP * 4);
    int* cur_pd      = (int*)bump((size_t)ND * 4);
    int* cur_dp      = (int*)bump((size_t)NP * 4);
    int* rp_pd       = (int*)bump((size_t)(ND + 1) * 4);
    int* rp_dp       = (int*)bump((size_t)(NP + 1) * 4);
    int* col_pd      = (int*)bump((size_t)EMAX * 4);
    int* col_dp      = (int*)bump((size_t)EMAX * 4);
    float* hd1       = (float*)bump((size_t)ND * 128 * 4);
    float* hd2       = (float*)bump((size_t)ND * 128 * 4);
    float* hp1       = (float*)bump((size_t)NP * 128 * 4);
    float* hp2       = (float*)bump((size_t)NP * 128 * 4);
    float* scr       = (float*)bump((size_t)ND * 128 * 4);

    float* out_p = (float*)d_out;
    float* out_d = out_p + (size_t)NP * 128;

    cudaMemsetAsync(cnt_p_out, 0, (size_t)NP * 4);
    cudaMemsetAsync(cnt_d_in, 0, (size_t)ND * 4);
    cudaMemsetAsync(cnt_d_out, 0, (size_t)ND * 4);
    cudaMemsetAsync(cnt_p_in, 0, (size_t)NP * 4);
    cudaMemsetAsync(cur_pd, 0, (size_t)ND * 4);
    cudaMemsetAsync(cur_dp, 0, (size_t)NP * 4);

    int Emax = (E > E2) ? E : E2;
    dim3 cg((Emax + 255) / 256, 4);
    count4<<<cg, 256>>>(pd_src, pd_dst, dp_src, dp_dst,
                        cnt_p_out, cnt_d_in, cnt_d_out, cnt_p_in, E, E, E2, E2);

    dim3 ig((NP + 255) / 256, 4);
    inv4<<<ig, 256>>>(cnt_p_out, cnt_d_in, cnt_d_out, cnt_p_in,
                      inv_p_out, inv_d_in, inv_d_out, inv_p_in, NP, ND, ND, NP);

    scan2<<<2, 1024>>>(cnt_d_in, rp_pd, ND, cnt_p_in, rp_dp, NP);

    dim3 fg((Emax + 255) / 256, 2);
    fill2<<<fg, 256>>>(pd_src, pd_dst, rp_pd, cur_pd, col_pd, E,
                       dp_src, dp_dst, rp_dp, cur_dp, col_dp, E2);

    const int AGG_D_GRID = (ND + 7) / 8;
    const int AGG_P_GRID = (NP + 7) / 8;
    const int GEMM_D_GRID = (ND + 127) / 128;

    auto pd_layer = [&](const float* xin, const float* W, const float* b, float* o) {
        agg_kernel<true, false><<<AGG_D_GRID, 256>>>(xin, rp_pd, col_pd, inv_p_out,
                                                     inv_d_in, nullptr, scr, ND);
        gemm128<false, true><<<GEMM_D_GRID, 256>>>(scr, W, nullptr, b, o, ND);
    };
    auto dp_layer = [&](const float* xin, const float* W, const float* b, float* o) {
        gemm128<true, false><<<GEMM_D_GRID, 256>>>(xin, W, inv_d_out, nullptr, scr, ND);
        agg_kernel<false, true><<<AGG_P_GRID, 256>>>(scr, rp_dp, col_dp, nullptr,
                                                     inv_p_in, b, o, NP);
    };

    pd_layer(h_p, W1_pd, b1_pd, hd1);
    dp_layer(h_d, W1_dp, b1_dp, hp1);
    pd_layer(hp1, W2_pd, b2_pd, hd2);
    dp_layer(hd1, W2_dp, b2_dp, hp2);
    pd_layer(hp2, W3_pd, b3_pd, out_d);
    dp_layer(hd2, W3_dp, b3_dp, out_p);
}

// round 8
// speedup vs baseline: 1.9862x; 1.2576x over previous
#include <cuda_runtime.h>

#define NP 100000
#define ND 50000
#define EMAX 600000

static const size_t TOTAL_BYTES = 256ull * 1024 * 1024;
__device__ __align__(256) unsigned char g_mem[TOTAL_BYTES];

// ---------------------------------------------------------------------------
// f32x2 helpers
// ---------------------------------------------------------------------------

__device__ __forceinline__ unsigned long long pk2dup(float x) {
    unsigned long long r;
    asm("mov.b64 %0, {%1, %1};" : "=l"(r) : "f"(x));
    return r;
}
__device__ __forceinline__ void fma2(unsigned long long& d, unsigned long long a,
                                     unsigned long long b) {
    asm("fma.rn.f32x2 %0, %1, %2, %0;" : "+l"(d) : "l"(a), "l"(b));
}
__device__ __forceinline__ float2 upk2(unsigned long long v) {
    float2 f;
    asm("mov.b64 {%0, %1}, %2;" : "=f"(f.x), "=f"(f.y) : "l"(v));
    return f;
}

// ---------------------------------------------------------------------------
// Fused setup kernels
// ---------------------------------------------------------------------------

__global__ void count4(const int* __restrict__ i0, const int* __restrict__ i1,
                       const int* __restrict__ i2, const int* __restrict__ i3,
                       int* __restrict__ c0, int* __restrict__ c1,
                       int* __restrict__ c2, int* __restrict__ c3,
                       int E0, int E1, int E2, int E3) {
    int e = blockIdx.x * blockDim.x + threadIdx.x;
    int y = blockIdx.y;
    const int* idx = (y == 0) ? i0 : (y == 1) ? i1 : (y == 2) ? i2 : i3;
    int* cnt = (y == 0) ? c0 : (y == 1) ? c1 : (y == 2) ? c2 : c3;
    int E = (y == 0) ? E0 : (y == 1) ? E1 : (y == 2) ? E2 : E3;
    if (e < E) atomicAdd(&cnt[idx[e]], 1);
}

__global__ void inv4(const int* __restrict__ c0, const int* __restrict__ c1,
                     const int* __restrict__ c2, const int* __restrict__ c3,
                     float* __restrict__ v0, float* __restrict__ v1,
                     float* __restrict__ v2, float* __restrict__ v3,
                     int n0, int n1, int n2, int n3) {
    int i = blockIdx.x * blockDim.x + threadIdx.x;
    int y = blockIdx.y;
    const int* cnt = (y == 0) ? c0 : (y == 1) ? c1 : (y == 2) ? c2 : c3;
    float* inv = (y == 0) ? v0 : (y == 1) ? v1 : (y == 2) ? v2 : v3;
    int n = (y == 0) ? n0 : (y == 1) ? n1 : (y == 2) ? n2 : n3;
    if (i < n) {
        int c = cnt[i];
        if (c < 1) c = 1;
        inv[i] = rsqrtf((float)c);
    }
}

__global__ void scan2(const int* __restrict__ cA, int* __restrict__ rpA, int nA,
                      const int* __restrict__ cB, int* __restrict__ rpB, int nB) {
    const int* cnt = blockIdx.x ? cB : cA;
    int* rowptr = blockIdx.x ? rpB : rpA;
    int n = blockIdx.x ? nB : nA;

    __shared__ int warp_sums[32];
    __shared__ int carry_s;
    int lane = threadIdx.x & 31;
    int warp = threadIdx.x >> 5;
    if (threadIdx.x == 0) { carry_s = 0; rowptr[0] = 0; }
    __syncthreads();
    for (int base = 0; base < n; base += 1024) {
        int i = base + (int)threadIdx.x;
        int v = (i < n) ? cnt[i] : 0;
        int x = v;
        #pragma unroll
        for (int off = 1; off < 32; off <<= 1) {
            int y = __shfl_up_sync(0xffffffffu, x, off);
            if (lane >= off) x += y;
        }
        if (lane == 31) warp_sums[warp] = x;
        __syncthreads();
        if (warp == 0) {
            int s = warp_sums[lane];
            #pragma unroll
            for (int off = 1; off < 32; off <<= 1) {
                int y = __shfl_up_sync(0xffffffffu, s, off);
                if (lane >= off) s += y;
            }
            warp_sums[lane] = s;
        }
        __syncthreads();
        int incl = carry_s + (warp ? warp_sums[warp - 1] : 0) + x;
        if (i < n) rowptr[i + 1] = incl;
        __syncthreads();
        if (threadIdx.x == 1023) carry_s = incl;
        __syncthreads();
    }
}

__global__ void fill2(const int* __restrict__ sA, const int* __restrict__ dA,
                      const int* __restrict__ rpA, int* __restrict__ curA,
                      int* __restrict__ colA, int EA,
                      const int* __restrict__ sB, const int* __restrict__ dB,
                      const int* __restrict__ rpB, int* __restrict__ curB,
                      int* __restrict__ colB, int EB) {
    int e = blockIdx.x * blockDim.x + threadIdx.x;
    const int* src = blockIdx.y ? sB : sA;
    const int* dst = blockIdx.y ? dB : dA;
    const int* rowptr = blockIdx.y ? rpB : rpA;
    int* cursor = blockIdx.y ? curB : curA;
    int* col = blockIdx.y ? colB : colA;
    int E = blockIdx.y ? EB : EA;
    if (e >= E) return;
    int d = dst[e];
    int pos = atomicAdd(&cursor[d], 1);
    col[rowptr[d] + pos] = src[e];
}

// ---------------------------------------------------------------------------
// Aggregation kernel (low regs, high occupancy, MLP-driven)
// ---------------------------------------------------------------------------

template <bool SRC_SCALE, bool BIAS_RELU>
__global__ void __launch_bounds__(256) agg_kernel(
    const float* __restrict__ x, const int* __restrict__ rowptr,
    const int* __restrict__ col, const float* __restrict__ inv_src,
    const float* __restrict__ inv_dst, const float* __restrict__ bias,
    float* __restrict__ out, int n) {
    int r = blockIdx.x * 8 + (int)(threadIdx.x >> 5);
    if (r >= n) return;
    int lane = threadIdx.x & 31;
    int s = rowptr[r], e = rowptr[r + 1];
    float a0 = 0.f, a1 = 0.f, a2 = 0.f, a3 = 0.f;
    int i = s;
    for (; i + 4 <= e; i += 4) {
        int c0 = col[i], c1 = col[i + 1], c2 = col[i + 2], c3 = col[i + 3];
        float4 v0 = *reinterpret_cast<const float4*>(x + c0 * 128 + lane * 4);
        float4 v1 = *reinterpret_cast<const float4*>(x + c1 * 128 + lane * 4);
        float4 v2 = *reinterpret_cast<const float4*>(x + c2 * 128 + lane * 4);
        float4 v3 = *reinterpret_cast<const float4*>(x + c3 * 128 + lane * 4);
        if (SRC_SCALE) {
            float s0 = inv_src[c0], s1 = inv_src[c1], s2 = inv_src[c2], s3 = inv_src[c3];
            a0 += v0.x * s0 + v1.x * s1 + v2.x * s2 + v3.x * s3;
            a1 += v0.y * s0 + v1.y * s1 + v2.y * s2 + v3.y * s3;
            a2 += v0.z * s0 + v1.z * s1 + v2.z * s2 + v3.z * s3;
            a3 += v0.w * s0 + v1.w * s1 + v2.w * s2 + v3.w * s3;
        } else {
            a0 += (v0.x + v1.x) + (v2.x + v3.x);
            a1 += (v0.y + v1.y) + (v2.y + v3.y);
            a2 += (v0.z + v1.z) + (v2.z + v3.z);
            a3 += (v0.w + v1.w) + (v2.w + v3.w);
        }
    }
    for (; i < e; i++) {
        int c0 = col[i];
        float4 v0 = *reinterpret_cast<const float4*>(x + c0 * 128 + lane * 4);
        float s0 = SRC_SCALE ? inv_src[c0] : 1.0f;
        a0 += v0.x * s0; a1 += v0.y * s0; a2 += v0.z * s0; a3 += v0.w * s0;
    }
    float sc = inv_dst[r];
    a0 *= sc; a1 *= sc; a2 *= sc; a3 *= sc;
    if (BIAS_RELU) {
        float4 bv = *reinterpret_cast<const float4*>(bias + lane * 4);
        a0 = fmaxf(a0 + bv.x, 0.f);
        a1 = fmaxf(a1 + bv.y, 0.f);
        a2 = fmaxf(a2 + bv.z, 0.f);
        a3 = fmaxf(a3 + bv.w, 0.f);
    }
    float4 o; o.x = a0; o.y = a1; o.z = a2; o.w = a3;
    *reinterpret_cast<float4*>(out + r * 128 + lane * 4) = o;
}

// ---------------------------------------------------------------------------
// GEMM kernel: BM=BN=128, BK=8, 8x8 microtile, FFMA2 with pack-free W operands
// ---------------------------------------------------------------------------

template <bool ROW_SCALE, bool BIAS_RELU>
__global__ void __launch_bounds__(256) gemm128(
    const float* __restrict__ A, const float* __restrict__ W,
    const float* __restrict__ rscale, const float* __restrict__ bias,
    float* __restrict__ out, int M) {
    __shared__ __align__(16) float As[8][128];
    __shared__ __align__(16) float Ws[8][128];
    int tid = threadIdx.x;
    int block_row = blockIdx.x * 128;
    int tm = (tid >> 4) << 3;
    int tn = (tid & 15) << 3;

    unsigned long long acc[8][4];
    #pragma unroll
    for (int i = 0; i < 8; i++)
        #pragma unroll
        for (int j = 0; j < 4; j++) acc[i][j] = 0ull;

    int ar = tid >> 1;
    int ap = (tid & 1) * 4;
    int wr = tid >> 5;
    int wc = (tid & 31) * 4;
    int gr_load = block_row + ar;

    float rs = 1.0f;
    if (ROW_SCALE && gr_load < M) rs = rscale[gr_load];

    for (int k0 = 0; k0 < 128; k0 += 8) {
        float4 av = make_float4(0.f, 0.f, 0.f, 0.f);
        if (gr_load < M)
            av = *reinterpret_cast<const float4*>(A + gr_load * 128 + k0 + ap);
        if (ROW_SCALE) { av.x *= rs; av.y *= rs; av.z *= rs; av.w *= rs; }
        As[ap + 0][ar] = av.x;
        As[ap + 1][ar] = av.y;
        As[ap + 2][ar] = av.z;
        As[ap + 3][ar] = av.w;
        *reinterpret_cast<float4*>(&Ws[wr][wc]) =
            *reinterpret_cast<const float4*>(W + (k0 + wr) * 128 + wc);
        __syncthreads();
        #pragma unroll
        for (int kk = 0; kk < 8; kk++) {
            ulonglong2 wA = *reinterpret_cast<ulonglong2*>(&Ws[kk][tn]);
            ulonglong2 wB = *reinterpret_cast<ulonglong2*>(&Ws[kk][tn + 4]);
            float4 a0 = *reinterpret_cast<float4*>(&As[kk][tm]);
            float4 a1 = *reinterpret_cast<float4*>(&As[kk][tm + 4]);
            float af[8] = {a0.x, a0.y, a0.z, a0.w, a1.x, a1.y, a1.z, a1.w};
            #pragma unroll
            for (int i = 0; i < 8; i++) {
                unsigned long long ai = pk2dup(af[i]);
                fma2(acc[i][0], ai, wA.x);
                fma2(acc[i][1], ai, wA.y);
                fma2(acc[i][2], ai, wB.x);
                fma2(acc[i][3], ai, wB.y);
            }
        }
        __syncthreads();
    }

    #pragma unroll
    for (int i = 0; i < 8; i++) {
        int gr = block_row + tm + i;
        if (gr >= M) continue;
        #pragma unroll
        for (int j = 0; j < 2; j++) {
            float2 p0 = upk2(acc[i][j * 2 + 0]);
            float2 p1 = upk2(acc[i][j * 2 + 1]);
            float4 v = make_float4(p0.x, p0.y, p1.x, p1.y);
            if (BIAS_RELU) {
                v.x = fmaxf(v.x + bias[tn + j * 4 + 0], 0.f);
                v.y = fmaxf(v.y + bias[tn + j * 4 + 1], 0.f);
                v.z = fmaxf(v.z + bias[tn + j * 4 + 2], 0.f);
                v.w = fmaxf(v.w + bias[tn + j * 4 + 3], 0.f);
            }
            *reinterpret_cast<float4*>(out + gr * 128 + tn + j * 4) = v;
        }
    }
}

// ---------------------------------------------------------------------------
// Launch: setup, then fork two independent GCN chains onto parallel streams.
// Chain A: h_p -> hd1 -> hp2 -> out_d     Chain B: h_d -> hp1 -> hd2 -> out_p
// ---------------------------------------------------------------------------

extern "C" void kernel_launch(void* const* d_in, const int* in_sizes, int n_in,
                              void* d_out, int out_size) {
    const float* h_p   = (const float*)d_in[0];
    const float* h_d   = (const float*)d_in[1];
    const int* pd_src  = (const int*)d_in[2];
    const int* pd_dst  = (const int*)d_in[3];
    const int* dp_src  = (const int*)d_in[4];
    const int* dp_dst  = (const int*)d_in[5];
    const float* W1_pd = (const float*)d_in[6];
    const float* b1_pd = (const float*)d_in[7];
    const float* W1_dp = (const float*)d_in[8];
    const float* b1_dp = (const float*)d_in[9];
    const float* W2_pd = (const float*)d_in[10];
    const float* b2_pd = (const float*)d_in[11];
    const float* W2_dp = (const float*)d_in[12];
    const float* b2_dp = (const float*)d_in[13];
    const float* W3_pd = (const float*)d_in[14];
    const float* b3_pd = (const float*)d_in[15];
    const float* W3_dp = (const float*)d_in[16];
    const float* b3_dp = (const float*)d_in[17];

    int E  = in_sizes[2];
    int E2 = in_sizes[4];

    void* base = nullptr;
    cudaGetSymbolAddress(&base, g_mem);
    unsigned char* p = (unsigned char*)base;
    auto bump = [&](size_t bytes) -> void* {
        void* r = (void*)p;
        p += (bytes + 255) & ~(size_t)255;
        return r;
    };

    float* inv_p_out = (float*)bump((size_t)NP * 4);
    float* inv_d_in  = (float*)bump((size_t)ND * 4);
    float* inv_d_out = (float*)bump((size_t)ND * 4);
    float* inv_p_in  = (float*)bump((size_t)NP * 4);
    unsigned char* zero_base = p;
    int* cnt_p_out   = (int*)bump((size_t)NP * 4);
    int* cnt_d_in    = (int*)bump((size_t)ND * 4);
    int* cnt_d_out   = (int*)bump((size_t)ND * 4);
    int* cnt_p_in    = (int*)bump((size_t)NP * 4);
    int* cur_pd      = (int*)bump((size_t)ND * 4);
    int* cur_dp      = (int*)bump((size_t)NP * 4);
    size_t zero_bytes = (size_t)(p - zero_base);
    int* rp_pd       = (int*)bump((size_t)(ND + 1) * 4);
    int* rp_dp       = (int*)bump((size_t)(NP + 1) * 4);
    int* col_pd      = (int*)bump((size_t)EMAX * 4);
    int* col_dp      = (int*)bump((size_t)EMAX * 4);
    float* hd1       = (float*)bump((size_t)ND * 128 * 4);
    float* hd2       = (float*)bump((size_t)ND * 128 * 4);
    float* hp1       = (float*)bump((size_t)NP * 128 * 4);
    float* hp2       = (float*)bump((size_t)NP * 128 * 4);
    float* scrA      = (float*)bump((size_t)ND * 128 * 4);
    float* scrB      = (float*)bump((size_t)ND * 128 * 4);

    float* out_p = (float*)d_out;
    float* out_d = out_p + (size_t)NP * 128;

    // --- setup (origin stream) ---
    cudaMemsetAsync(zero_base, 0, zero_bytes);

    int Emax = (E > E2) ? E : E2;
    dim3 cg((Emax + 255) / 256, 4);
    count4<<<cg, 256>>>(pd_src, pd_dst, dp_src, dp_dst,
                        cnt_p_out, cnt_d_in, cnt_d_out, cnt_p_in, E, E, E2, E2);

    dim3 ig((NP + 255) / 256, 4);
    inv4<<<ig, 256>>>(cnt_p_out, cnt_d_in, cnt_d_out, cnt_p_in,
                      inv_p_out, inv_d_in, inv_d_out, inv_p_in, NP, ND, ND, NP);

    scan2<<<2, 1024>>>(cnt_d_in, rp_pd, ND, cnt_p_in, rp_dp, NP);

    dim3 fg((Emax + 255) / 256, 2);
    fill2<<<fg, 256>>>(pd_src, pd_dst, rp_pd, cur_pd, col_pd, E,
                       dp_src, dp_dst, rp_dp, cur_dp, col_dp, E2);

    const int AGG_D_GRID = (ND + 7) / 8;
    const int AGG_P_GRID = (NP + 7) / 8;
    const int GEMM_D_GRID = (ND + 127) / 128;

    // --- fork second stream for chain B ---
    cudaStream_t s2;
    cudaEvent_t evFork, evJoin;
    cudaStreamCreateWithFlags(&s2, cudaStreamNonBlocking);
    cudaEventCreateWithFlags(&evFork, cudaEventDisableTiming);
    cudaEventCreateWithFlags(&evJoin, cudaEventDisableTiming);
    cudaEventRecord(evFork, 0);
    cudaStreamWaitEvent(s2, evFork, 0);

    auto pd_step = [&](cudaStream_t st, float* scr, const float* xin,
                       const float* W, const float* b, float* o) {
        agg_kernel<true, false><<<AGG_D_GRID, 256, 0, st>>>(
            xin, rp_pd, col_pd, inv_p_out, inv_d_in, nullptr, scr, ND);
        gemm128<false, true><<<GEMM_D_GRID, 256, 0, st>>>(scr, W, nullptr, b, o, ND);
    };
    auto dp_step = [&](cudaStream_t st, float* scr, const float* xin,
                       const float* W, const float* b, float* o) {
        gemm128<true, false><<<GEMM_D_GRID, 256, 0, st>>>(
            xin, W, inv_d_out, nullptr, scr, ND);
        agg_kernel<false, true><<<AGG_P_GRID, 256, 0, st>>>(
            scr, rp_dp, col_dp, nullptr, inv_p_in, b, o, NP);
    };

    // Chain A on origin stream: h_p -> hd1 -> hp2 -> out_d
    pd_step((cudaStream_t)0, scrA, h_p, W1_pd, b1_pd, hd1);
    dp_step((cudaStream_t)0, scrA, hd1, W2_dp, b2_dp, hp2);
    pd_step((cudaStream_t)0, scrA, hp2, W3_pd, b3_pd, out_d);

    // Chain B on s2: h_d -> hp1 -> hd2 -> out_p
    dp_step(s2, scrB, h_d, W1_dp, b1_dp, hp1);
    pd_step(s2, scrB, hp1, W2_pd, b2_pd, hd2);
    dp_step(s2, scrB, hd2, W3_dp, b3_dp, out_p);

    // --- join back to origin stream ---
    cudaEventRecord(evJoin, s2);
    cudaStreamWaitEvent((cudaStream_t)0, evJoin, 0);
}

// round 11
// speedup vs baseline: 2.0703x; 1.0424x over previous
#include <cuda_runtime.h>
#include <cuda_fp16.h>

#define NP 100000
#define ND 50000
#define EMAX 600000

static const size_t TOTAL_BYTES = 256ull * 1024 * 1024;
__device__ __align__(256) unsigned char g_mem[TOTAL_BYTES];

// ---------------------------------------------------------------------------
// f32x2 helpers
// ---------------------------------------------------------------------------

__device__ __forceinline__ unsigned long long pk2dup(float x) {
    unsigned long long r;
    asm("mov.b64 %0, {%1, %1};" : "=l"(r) : "f"(x));
    return r;
}
__device__ __forceinline__ void fma2(unsigned long long& d, unsigned long long a,
                                     unsigned long long b) {
    asm("fma.rn.f32x2 %0, %1, %2, %0;" : "+l"(d) : "l"(a), "l"(b));
}
__device__ __forceinline__ float2 upk2(unsigned long long v) {
    float2 f;
    asm("mov.b64 {%0, %1}, %2;" : "=f"(f.x), "=f"(f.y) : "l"(v));
    return f;
}

// ---------------------------------------------------------------------------
// Fused setup kernels
// ---------------------------------------------------------------------------

__global__ void count4(const int* __restrict__ i0, const int* __restrict__ i1,
                       const int* __restrict__ i2, const int* __restrict__ i3,
                       int* __restrict__ c0, int* __restrict__ c1,
                       int* __restrict__ c2, int* __restrict__ c3,
                       int E0, int E1, int E2, int E3) {
    int e = blockIdx.x * blockDim.x + threadIdx.x;
    int y = blockIdx.y;
    const int* idx = (y == 0) ? i0 : (y == 1) ? i1 : (y == 2) ? i2 : i3;
    int* cnt = (y == 0) ? c0 : (y == 1) ? c1 : (y == 2) ? c2 : c3;
    int E = (y == 0) ? E0 : (y == 1) ? E1 : (y == 2) ? E2 : E3;
    if (e < E) atomicAdd(&cnt[idx[e]], 1);
}

__global__ void inv4(const int* __restrict__ c0, const int* __restrict__ c1,
                     const int* __restrict__ c2, const int* __restrict__ c3,
                     float* __restrict__ v0, float* __restrict__ v1,
                     float* __restrict__ v2, float* __restrict__ v3,
                     int n0, int n1, int n2, int n3) {
    int i = blockIdx.x * blockDim.x + threadIdx.x;
    int y = blockIdx.y;
    const int* cnt = (y == 0) ? c0 : (y == 1) ? c1 : (y == 2) ? c2 : c3;
    float* inv = (y == 0) ? v0 : (y == 1) ? v1 : (y == 2) ? v2 : v3;
    int n = (y == 0) ? n0 : (y == 1) ? n1 : (y == 2) ? n2 : n3;
    if (i < n) {
        int c = cnt[i];
        if (c < 1) c = 1;
        inv[i] = rsqrtf((float)c);
    }
}

__global__ void scan2(const int* __restrict__ cA, int* __restrict__ rpA, int nA,
                      const int* __restrict__ cB, int* __restrict__ rpB, int nB) {
    const int* cnt = blockIdx.x ? cB : cA;
    int* rowptr = blockIdx.x ? rpB : rpA;
    int n = blockIdx.x ? nB : nA;

    __shared__ int warp_sums[32];
    __shared__ int carry_s;
    int lane = threadIdx.x & 31;
    int warp = threadIdx.x >> 5;
    if (threadIdx.x == 0) { carry_s = 0; rowptr[0] = 0; }
    __syncthreads();
    for (int base = 0; base < n; base += 1024) {
        int i = base + (int)threadIdx.x;
        int v = (i < n) ? cnt[i] : 0;
        int x = v;
        #pragma unroll
        for (int off = 1; off < 32; off <<= 1) {
            int y = __shfl_up_sync(0xffffffffu, x, off);
            if (lane >= off) x += y;
        }
        if (lane == 31) warp_sums[warp] = x;
        __syncthreads();
        if (warp == 0) {
            int s = warp_sums[lane];
            #pragma unroll
            for (int off = 1; off < 32; off <<= 1) {
                int y = __shfl_up_sync(0xffffffffu, s, off);
                if (lane >= off) s += y;
            }
            warp_sums[lane] = s;
        }
        __syncthreads();
        int incl = carry_s + (warp ? warp_sums[warp - 1] : 0) + x;
        if (i < n) rowptr[i + 1] = incl;
        __syncthreads();
        if (threadIdx.x == 1023) carry_s = incl;
        __syncthreads();
    }
}

__global__ void fill2(const int* __restrict__ sA, const int* __restrict__ dA,
                      const int* __restrict__ rpA, int* __restrict__ curA,
                      int* __restrict__ colA, int EA,
                      const int* __restrict__ sB, const int* __restrict__ dB,
                      const int* __restrict__ rpB, int* __restrict__ curB,
                      int* __restrict__ colB, int EB) {
    int e = blockIdx.x * blockDim.x + threadIdx.x;
    const int* src = blockIdx.y ? sB : sA;
    const int* dst = blockIdx.y ? dB : dA;
    const int* rowptr = blockIdx.y ? rpB : rpA;
    int* cursor = blockIdx.y ? curB : curA;
    int* col = blockIdx.y ? colB : colA;
    int E = blockIdx.y ? EB : EA;
    if (e >= E) return;
    int d = dst[e];
    int pos = atomicAdd(&cursor[d], 1);
    col[rowptr[d] + pos] = src[e];
}

// fp32 -> fp16 table convert (n = element count / 4)
__global__ void f2h(const float* __restrict__ in, __half* __restrict__ out, int n) {
    int i = blockIdx.x * blockDim.x + threadIdx.x;
    if (i < n) {
        float4 v = reinterpret_cast<const float4*>(in)[i];
        __half2 h0 = __floats2half2_rn(v.x, v.y);
        __half2 h1 = __floats2half2_rn(v.z, v.w);
        uint2 o;
        o.x = *reinterpret_cast<unsigned int*>(&h0);
        o.y = *reinterpret_cast<unsigned int*>(&h1);
        reinterpret_cast<uint2*>(out)[i] = o;
    }
}

// ---------------------------------------------------------------------------
// Aggregation kernel — fp16 gather tables, fp32 accumulation.
// 32 threads per row (4 features/lane, 8-byte loads), 8 rows per block.
// ---------------------------------------------------------------------------

__device__ __forceinline__ void acc4h(float& a0, float& a1, float& a2, float& a3,
                                      uint2 v, float s) {
    __half2 h0 = *reinterpret_cast<__half2*>(&v.x);
    __half2 h1 = *reinterpret_cast<__half2*>(&v.y);
    float2 f0 = __half22float2(h0);
    float2 f1 = __half22float2(h1);
    a0 += f0.x * s; a1 += f0.y * s; a2 += f1.x * s; a3 += f1.y * s;
}

template <bool SRC_SCALE, bool BIAS_RELU, bool OUT_HALF>
__global__ void __launch_bounds__(256) agg_h(
    const __half* __restrict__ x, const int* __restrict__ rowptr,
    const int* __restrict__ col, const float* __restrict__ inv_src,
    const float* __restrict__ inv_dst, const float* __restrict__ bias,
    void* __restrict__ out_, int n) {
    int r = blockIdx.x * 8 + (int)(threadIdx.x >> 5);
    if (r >= n) return;
    int lane = threadIdx.x & 31;
    int s = rowptr[r], e = rowptr[r + 1];
    float a0 = 0.f, a1 = 0.f, a2 = 0.f, a3 = 0.f;
    int i = s;
    for (; i + 4 <= e; i += 4) {
        int c0 = col[i], c1 = col[i + 1], c2 = col[i + 2], c3 = col[i + 3];
        uint2 v0 = *reinterpret_cast<const uint2*>(x + c0 * 128 + lane * 4);
        uint2 v1 = *reinterpret_cast<const uint2*>(x + c1 * 128 + lane * 4);
        uint2 v2 = *reinterpret_cast<const uint2*>(x + c2 * 128 + lane * 4);
        uint2 v3 = *reinterpret_cast<const uint2*>(x + c3 * 128 + lane * 4);
        float s0 = SRC_SCALE ? inv_src[c0] : 1.0f;
        float s1 = SRC_SCALE ? inv_src[c1] : 1.0f;
        float s2 = SRC_SCALE ? inv_src[c2] : 1.0f;
        float s3 = SRC_SCALE ? inv_src[c3] : 1.0f;
        acc4h(a0, a1, a2, a3, v0, s0);
        acc4h(a0, a1, a2, a3, v1, s1);
        acc4h(a0, a1, a2, a3, v2, s2);
        acc4h(a0, a1, a2, a3, v3, s3);
    }
    for (; i < e; i++) {
        int c0 = col[i];
        uint2 v0 = *reinterpret_cast<const uint2*>(x + c0 * 128 + lane * 4);
        float s0 = SRC_SCALE ? inv_src[c0] : 1.0f;
        acc4h(a0, a1, a2, a3, v0, s0);
    }
    float sc = inv_dst[r];
    a0 *= sc; a1 *= sc; a2 *= sc; a3 *= sc;
    if (BIAS_RELU) {
        float4 bv = *reinterpret_cast<const float4*>(bias + lane * 4);
        a0 = fmaxf(a0 + bv.x, 0.f);
        a1 = fmaxf(a1 + bv.y, 0.f);
        a2 = fmaxf(a2 + bv.z, 0.f);
        a3 = fmaxf(a3 + bv.w, 0.f);
    }
    if (OUT_HALF) {
        __half2 o0 = __floats2half2_rn(a0, a1);
        __half2 o1 = __floats2half2_rn(a2, a3);
        uint2 o;
        o.x = *reinterpret_cast<unsigned int*>(&o0);
        o.y = *reinterpret_cast<unsigned int*>(&o1);
        *reinterpret_cast<uint2*>((__half*)out_ + r * 128 + lane * 4) = o;
    } else {
        float4 o; o.x = a0; o.y = a1; o.z = a2; o.w = a3;
        *reinterpret_cast<float4*>((float*)out_ + r * 128 + lane * 4) = o;
    }
}

// ---------------------------------------------------------------------------
// GEMM kernel: fp32 in, fp32 or fp16 out. BM=BN=128, BK=8, 8x8 microtile, FFMA2.
// ---------------------------------------------------------------------------

template <bool ROW_SCALE, bool BIAS_RELU, bool OUT_HALF>
__global__ void __launch_bounds__(256) gemm128(
    const float* __restrict__ A, const float* __restrict__ W,
    const float* __restrict__ rscale, const float* __restrict__ bias,
    void* __restrict__ out_, int M) {
    __shared__ __align__(16) float As[8][128];
    __shared__ __align__(16) float Ws[8][128];
    int tid = threadIdx.x;
    int block_row = blockIdx.x * 128;
    int tm = (tid >> 4) << 3;
    int tn = (tid & 15) << 3;

    unsigned long long acc[8][4];
    #pragma unroll
    for (int i = 0; i < 8; i++)
        #pragma unroll
        for (int j = 0; j < 4; j++) acc[i][j] = 0ull;

    int ar = tid >> 1;
    int ap = (tid & 1) * 4;
    int wr = tid >> 5;
    int wc = (tid & 31) * 4;
    int gr_load = block_row + ar;

    float rs = 1.0f;
    if (ROW_SCALE && gr_load < M) rs = rscale[gr_load];

    for (int k0 = 0; k0 < 128; k0 += 8) {
        float4 av = make_float4(0.f, 0.f, 0.f, 0.f);
        if (gr_load < M)
            av = *reinterpret_cast<const float4*>(A + gr_load * 128 + k0 + ap);
        if (ROW_SCALE) { av.x *= rs; av.y *= rs; av.z *= rs; av.w *= rs; }
        As[ap + 0][ar] = av.x;
        As[ap + 1][ar] = av.y;
        As[ap + 2][ar] = av.z;
        As[ap + 3][ar] = av.w;
        *reinterpret_cast<float4*>(&Ws[wr][wc]) =
            *reinterpret_cast<const float4*>(W + (k0 + wr) * 128 + wc);
        __syncthreads();
        #pragma unroll
        for (int kk = 0; kk < 8; kk++) {
            ulonglong2 wA = *reinterpret_cast<ulonglong2*>(&Ws[kk][tn]);
            ulonglong2 wB = *reinterpret_cast<ulonglong2*>(&Ws[kk][tn + 4]);
            float4 a0 = *reinterpret_cast<float4*>(&As[kk][tm]);
            float4 a1 = *reinterpret_cast<float4*>(&As[kk][tm + 4]);
            float af[8] = {a0.x, a0.y, a0.z, a0.w, a1.x, a1.y, a1.z, a1.w};
            #pragma unroll
            for (int i = 0; i < 8; i++) {
                unsigned long long ai = pk2dup(af[i]);
                fma2(acc[i][0], ai, wA.x);
                fma2(acc[i][1], ai, wA.y);
                fma2(acc[i][2], ai, wB.x);
                fma2(acc[i][3], ai, wB.y);
            }
        }
        __syncthreads();
    }

    #pragma unroll
    for (int i = 0; i < 8; i++) {
        int gr = block_row + tm + i;
        if (gr >= M) continue;
        float2 p[4];
        #pragma unroll
        for (int j = 0; j < 4; j++) p[j] = upk2(acc[i][j]);
        if (BIAS_RELU) {
            #pragma unroll
            for (int j = 0; j < 4; j++) {
                p[j].x = fmaxf(p[j].x + bias[tn + j * 2 + 0], 0.f);
                p[j].y = fmaxf(p[j].y + bias[tn + j * 2 + 1], 0.f);
            }
        }
        if (OUT_HALF) {
            uint4 o;
            __half2 h0 = __floats2half2_rn(p[0].x, p[0].y);
            __half2 h1 = __floats2half2_rn(p[1].x, p[1].y);
            __half2 h2 = __floats2half2_rn(p[2].x, p[2].y);
            __half2 h3 = __floats2half2_rn(p[3].x, p[3].y);
            o.x = *reinterpret_cast<unsigned int*>(&h0);
            o.y = *reinterpret_cast<unsigned int*>(&h1);
            o.z = *reinterpret_cast<unsigned int*>(&h2);
            o.w = *reinterpret_cast<unsigned int*>(&h3);
            *reinterpret_cast<uint4*>((__half*)out_ + (size_t)gr * 128 + tn) = o;
        } else {
            float* out = (float*)out_;
            *reinterpret_cast<float4*>(out + (size_t)gr * 128 + tn) =
                make_float4(p[0].x, p[0].y, p[1].x, p[1].y);
            *reinterpret_cast<float4*>(out + (size_t)gr * 128 + tn + 4) =
                make_float4(p[2].x, p[2].y, p[3].x, p[3].y);
        }
    }
}

// ---------------------------------------------------------------------------
// Launch: setup, then two independent GCN chains on parallel streams.
// Chain A: h_p -> hd1 -> hp2 -> out_d     Chain B: h_d -> hp1 -> hd2 -> out_p
// All gather tables fp16; GEMM inputs + final outputs fp32.
// ---------------------------------------------------------------------------

extern "C" void kernel_launch(void* const* d_in, const int* in_sizes, int n_in,
                              void* d_out, int out_size) {
    const float* h_p   = (const float*)d_in[0];
    const float* h_d   = (const float*)d_in[1];
    const int* pd_src  = (const int*)d_in[2];
    const int* pd_dst  = (const int*)d_in[3];
    const int* dp_src  = (const int*)d_in[4];
    const int* dp_dst  = (const int*)d_in[5];
    const float* W1_pd = (const float*)d_in[6];
    const float* b1_pd = (const float*)d_in[7];
    const float* W1_dp = (const float*)d_in[8];
    const float* b1_dp = (const float*)d_in[9];
    const float* W2_pd = (const float*)d_in[10];
    const float* b2_pd = (const float*)d_in[11];
    const float* W2_dp = (const float*)d_in[12];
    const float* b2_dp = (const float*)d_in[13];
    const float* W3_pd = (const float*)d_in[14];
    const float* b3_pd = (const float*)d_in[15];
    const float* W3_dp = (const float*)d_in[16];
    const float* b3_dp = (const float*)d_in[17];

    int E  = in_sizes[2];
    int E2 = in_sizes[4];

    void* base = nullptr;
    cudaGetSymbolAddress(&base, g_mem);
    unsigned char* p = (unsigned char*)base;
    auto bump = [&](size_t bytes) -> void* {
        void* r = (void*)p;
        p += (bytes + 255) & ~(size_t)255;
        return r;
    };

    float* inv_p_out = (float*)bump((size_t)NP * 4);
    float* inv_d_in  = (float*)bump((size_t)ND * 4);
    float* inv_d_out = (float*)bump((size_t)ND * 4);
    float* inv_p_in  = (float*)bump((size_t)NP * 4);
    unsigned char* zero_base = p;
    int* cnt_p_out   = (int*)bump((size_t)NP * 4);
    int* cnt_d_in    = (int*)bump((size_t)ND * 4);
    int* cnt_d_out   = (int*)bump((size_t)ND * 4);
    int* cnt_p_in    = (int*)bump((size_t)NP * 4);
    int* cur_pd      = (int*)bump((size_t)ND * 4);
    int* cur_dp      = (int*)bump((size_t)NP * 4);
    size_t zero_bytes = (size_t)(p - zero_base);
    int* rp_pd       = (int*)bump((size_t)(ND + 1) * 4);
    int* rp_dp       = (int*)bump((size_t)(NP + 1) * 4);
    int* col_pd      = (int*)bump((size_t)EMAX * 4);
    int* col_dp      = (int*)bump((size_t)EMAX * 4);
    __half* h_ph     = (__half*)bump((size_t)NP * 128 * 2);   // fp16 copy of h_p
    __half* hp1h     = (__half*)bump((size_t)NP * 128 * 2);
    __half* hp2h     = (__half*)bump((size_t)NP * 128 * 2);
    __half* gscrA    = (__half*)bump((size_t)ND * 128 * 2);   // gemm_dp out (A)
    __half* gscrB    = (__half*)bump((size_t)ND * 128 * 2);   // gemm_dp out (B)
    float* scrA      = (float*)bump((size_t)ND * 128 * 4);    // agg_pd out (A)
    float* scrB      = (float*)bump((size_t)ND * 128 * 4);    // agg_pd out (B)
    float* hd1       = (float*)bump((size_t)ND * 128 * 4);
    float* hd2       = (float*)bump((size_t)ND * 128 * 4);

    float* out_p = (float*)d_out;
    float* out_d = out_p + (size_t)NP * 128;

    // --- setup (origin stream) ---
    cudaMemsetAsync(zero_base, 0, zero_bytes);

    f2h<<<(NP * 128 / 4 + 255) / 256, 256>>>(h_p, h_ph, NP * 128 / 4);

    int Emax = (E > E2) ? E : E2;
    dim3 cg((Emax + 255) / 256, 4);
    count4<<<cg, 256>>>(pd_src, pd_dst, dp_src, dp_dst,
                        cnt_p_out, cnt_d_in, cnt_d_out, cnt_p_in, E, E, E2, E2);

    dim3 ig((NP + 255) / 256, 4);
    inv4<<<ig, 256>>>(cnt_p_out, cnt_d_in, cnt_d_out, cnt_p_in,
                      inv_p_out, inv_d_in, inv_d_out, inv_p_in, NP, ND, ND, NP);

    scan2<<<2, 1024>>>(cnt_d_in, rp_pd, ND, cnt_p_in, rp_dp, NP);

    dim3 fg((Emax + 255) / 256, 2);
    fill2<<<fg, 256>>>(pd_src, pd_dst, rp_pd, cur_pd, col_pd, E,
                       dp_src, dp_dst, rp_dp, cur_dp, col_dp, E2);

    const int AGG_D_GRID = (ND + 7) / 8;
    const int AGG_P_GRID = (NP + 7) / 8;
    const int GEMM_D_GRID = (ND + 127) / 128;

    // --- fork second stream for chain B ---
    cudaStream_t s2;
    cudaEvent_t evFork, evJoin;
    cudaStreamCreateWithFlags(&s2, cudaStreamNonBlocking);
    cudaEventCreateWithFlags(&evFork, cudaEventDisableTiming);
    cudaEventCreateWithFlags(&evJoin, cudaEventDisableTiming);
    cudaEventRecord(evFork, 0);
    cudaStreamWaitEvent(s2, evFork, 0);

    // pd: agg(x_half) -> scr(fp32); gemm+bias+relu -> o (fp32 or any)
    auto pd_step = [&](cudaStream_t st, float* scr, const __half* xin,
                       const float* W, const float* b, void* o, bool ohalf) {
        agg_h<true, false, false><<<AGG_D_GRID, 256, 0, st>>>(
            xin, rp_pd, col_pd, inv_p_out, inv_d_in, nullptr, scr, ND);
        gemm128<false, true, false><<<GEMM_D_GRID, 256, 0, st>>>(
            scr, W, nullptr, b, o, ND);
        (void)ohalf;
    };
    // dp: gemm(x fp32, rscale) -> gscr(half); agg+bias+relu -> o
    auto dp_step = [&](cudaStream_t st, __half* gscr, const float* xin,
                       const float* W, const float* b, void* o, bool ohalf) {
        gemm128<true, false, true><<<GEMM_D_GRID, 256, 0, st>>>(
            xin, W, inv_d_out, nullptr, gscr, ND);
        if (ohalf)
            agg_h<false, true, true><<<AGG_P_GRID, 256, 0, st>>>(
                gscr, rp_dp, col_dp, nullptr, inv_p_in, b, o, NP);
        else
            agg_h<false, true, false><<<AGG_P_GRID, 256, 0, st>>>(
                gscr, rp_dp, col_dp, nullptr, inv_p_in, b, o, NP);
    };

    // Chain A (origin stream): h_p -> hd1 -> hp2 -> out_d
    pd_step((cudaStream_t)0, scrA, h_ph, W1_pd, b1_pd, hd1, false);
    dp_step((cudaStream_t)0, gscrA, hd1, W2_dp, b2_dp, hp2h, true);
    pd_step((cudaStream_t)0, scrA, hp2h, W3_pd, b3_pd, out_d, false);

    // Chain B (s2): h_d -> hp1 -> hd2 -> out_p
    dp_step(s2, gscrB, h_d, W1_dp, b1_dp, hp1h, true);
    pd_step(s2, scrB, hp1h, W2_pd, b2_pd, hd2, false);
    dp_step(s2, gscrB, hd2, W3_dp, b3_dp, out_p, false);

    // --- join ---
    cudaEventRecord(evJoin, s2);
    cudaStreamWaitEvent((cudaStream_t)0, evJoin, 0);
}

// round 14
// speedup vs baseline: 2.3451x; 1.1327x over previous
#include <cuda_runtime.h>
#include <cuda_fp16.h>

#define NP 100000
#define ND 50000
#define EMAX 600000

static const size_t TOTAL_BYTES = 256ull * 1024 * 1024;
__device__ __align__(256) unsigned char g_mem[TOTAL_BYTES];

// ---------------------------------------------------------------------------
// f32x2 helpers
// ---------------------------------------------------------------------------

__device__ __forceinline__ unsigned long long pk2dup(float x) {
    unsigned long long r;
    asm("mov.b64 %0, {%1, %1};" : "=l"(r) : "f"(x));
    return r;
}
__device__ __forceinline__ void fma2(unsigned long long& d, unsigned long long a,
                                     unsigned long long b) {
    asm("fma.rn.f32x2 %0, %1, %2, %0;" : "+l"(d) : "l"(a), "l"(b));
}
__device__ __forceinline__ float2 upk2(unsigned long long v) {
    float2 f;
    asm("mov.b64 {%0, %1}, %2;" : "=f"(f.x), "=f"(f.y) : "l"(v));
    return f;
}

// ---------------------------------------------------------------------------
// Setup kernels
// ---------------------------------------------------------------------------

__global__ void count4(const int* __restrict__ i0, const int* __restrict__ i1,
                       const int* __restrict__ i2, const int* __restrict__ i3,
                       int* __restrict__ c0, int* __restrict__ c1,
                       int* __restrict__ c2, int* __restrict__ c3,
                       int E0, int E1, int E2, int E3) {
    int e = blockIdx.x * blockDim.x + threadIdx.x;
    int y = blockIdx.y;
    const int* idx = (y == 0) ? i0 : (y == 1) ? i1 : (y == 2) ? i2 : i3;
    int* cnt = (y == 0) ? c0 : (y == 1) ? c1 : (y == 2) ? c2 : c3;
    int E = (y == 0) ? E0 : (y == 1) ? E1 : (y == 2) ? E2 : E3;
    if (e < E) atomicAdd(&cnt[idx[e]], 1);
}

__global__ void inv4(const int* __restrict__ c0, const int* __restrict__ c1,
                     const int* __restrict__ c2, const int* __restrict__ c3,
                     float* __restrict__ v0, float* __restrict__ v1,
                     float* __restrict__ v2, float* __restrict__ v3,
                     int n0, int n1, int n2, int n3) {
    int i = blockIdx.x * blockDim.x + threadIdx.x;
    int y = blockIdx.y;
    const int* cnt = (y == 0) ? c0 : (y == 1) ? c1 : (y == 2) ? c2 : c3;
    float* inv = (y == 0) ? v0 : (y == 1) ? v1 : (y == 2) ? v2 : v3;
    int n = (y == 0) ? n0 : (y == 1) ? n1 : (y == 2) ? n2 : n3;
    if (i < n) {
        int c = cnt[i];
        if (c < 1) c = 1;
        inv[i] = rsqrtf((float)c);
    }
}

// --- 3-phase parallel scan (replaces 2-block serial scan2, was 89.7us) ---

// Phase 1: per-block (1024) inclusive scan, emit partials + per-block sums.
__global__ void scan_up(const int* __restrict__ cA, int* __restrict__ pA,
                        int* __restrict__ sA, int nA,
                        const int* __restrict__ cB, int* __restrict__ pB,
                        int* __restrict__ sB, int nB) {
    const int* cnt = blockIdx.y ? cB : cA;
    int* part = blockIdx.y ? pB : pA;
    int* sums = blockIdx.y ? sB : sA;
    int n = blockIdx.y ? nB : nA;

    __shared__ int ws[32];
    int lane = threadIdx.x & 31;
    int warp = threadIdx.x >> 5;
    int i = blockIdx.x * 1024 + (int)threadIdx.x;
    int v = (i < n) ? cnt[i] : 0;
    int x = v;
    #pragma unroll
    for (int off = 1; off < 32; off <<= 1) {
        int y = __shfl_up_sync(0xffffffffu, x, off);
        if (lane >= off) x += y;
    }
    if (lane == 31) ws[warp] = x;
    __syncthreads();
    if (warp == 0) {
        int s = ws[lane];
        #pragma unroll
        for (int off = 1; off < 32; off <<= 1) {
            int y = __shfl_up_sync(0xffffffffu, s, off);
            if (lane >= off) s += y;
        }
        ws[lane] = s;
    }
    __syncthreads();
    int incl = x + (warp ? ws[warp - 1] : 0);
    if (i < n) part[i] = incl;
    if (threadIdx.x == 1023) sums[blockIdx.x] = incl;
}

// Phase 2: one block per array scans its block-sums (<=128) to exclusive offsets.
__global__ void scan_mid(int* __restrict__ sA, int nA, int* __restrict__ sB, int nB) {
    int* s = blockIdx.x ? sB : sA;
    int n = blockIdx.x ? nB : nA;  // number of block sums
    __shared__ int ws[4];
    int lane = threadIdx.x & 31;
    int warp = threadIdx.x >> 5;
    int v = ((int)threadIdx.x < n) ? s[threadIdx.x] : 0;
    int x = v;
    #pragma unroll
    for (int off = 1; off < 32; off <<= 1) {
        int y = __shfl_up_sync(0xffffffffu, x, off);
        if (lane >= off) x += y;
    }
    if (lane == 31) ws[warp] = x;
    __syncthreads();
    int add = 0;
    for (int w = 0; w < warp; w++) add += ws[w];
    int excl = x + add - v;
    if ((int)threadIdx.x < n) s[threadIdx.x] = excl;
}

// Phase 3: rowptr[i+1] = part[i] + offset[block]; rowptr[0] = 0.
__global__ void scan_down(const int* __restrict__ pA, const int* __restrict__ sA,
                          int* __restrict__ rpA, int nA,
                          const int* __restrict__ pB, const int* __restrict__ sB,
                          int* __restrict__ rpB, int nB) {
    const int* part = blockIdx.y ? pB : pA;
    const int* sums = blockIdx.y ? sB : sA;
    int* rowptr = blockIdx.y ? rpB : rpA;
    int n = blockIdx.y ? nB : nA;
    int i = blockIdx.x * 1024 + (int)threadIdx.x;
    if (i < n) rowptr[i + 1] = part[i] + sums[blockIdx.x];
    if (i == 0) rowptr[0] = 0;
}

__global__ void fill2(const int* __restrict__ sA, const int* __restrict__ dA,
                      const int* __restrict__ rpA, int* __restrict__ curA,
                      int* __restrict__ colA, int EA,
                      const int* __restrict__ sB, const int* __restrict__ dB,
                      const int* __restrict__ rpB, int* __restrict__ curB,
                      int* __restrict__ colB, int EB) {
    int e = blockIdx.x * blockDim.x + threadIdx.x;
    const int* src = blockIdx.y ? sB : sA;
    const int* dst = blockIdx.y ? dB : dA;
    const int* rowptr = blockIdx.y ? rpB : rpA;
    int* cursor = blockIdx.y ? curB : curA;
    int* col = blockIdx.y ? colB : colA;
    int E = blockIdx.y ? EB : EA;
    if (e >= E) return;
    int d = dst[e];
    int pos = atomicAdd(&cursor[d], 1);
    col[rowptr[d] + pos] = src[e];
}

// fp32 -> fp16 table convert with per-row pre-scale by inv_p_out.
// i indexes float4 groups; row = i >> 5 (32 groups of 4 per 128-wide row).
__global__ void f2h_scaled(const float* __restrict__ in, __half* __restrict__ out,
                           const float* __restrict__ rscale, int n) {
    int i = blockIdx.x * blockDim.x + threadIdx.x;
    if (i < n) {
        float s = rscale[i >> 5];
        float4 v = reinterpret_cast<const float4*>(in)[i];
        __half2 h0 = __floats2half2_rn(v.x * s, v.y * s);
        __half2 h1 = __floats2half2_rn(v.z * s, v.w * s);
        uint2 o;
        o.x = *reinterpret_cast<unsigned int*>(&h0);
        o.y = *reinterpret_cast<unsigned int*>(&h1);
        reinterpret_cast<uint2*>(out)[i] = o;
    }
}

// ---------------------------------------------------------------------------
// Aggregation: fp16 pre-scaled gather tables, fp32 accumulation, pure sum.
// 32 threads/row (4 features/lane via uint2), 8 rows/block.
// ---------------------------------------------------------------------------

__device__ __forceinline__ void acc4h(float& a0, float& a1, float& a2, float& a3,
                                      uint2 v) {
    __half2 h0 = *reinterpret_cast<__half2*>(&v.x);
    __half2 h1 = *reinterpret_cast<__half2*>(&v.y);
    float2 f0 = __half22float2(h0);
    float2 f1 = __half22float2(h1);
    a0 += f0.x; a1 += f0.y; a2 += f1.x; a3 += f1.y;
}

template <bool BIAS_RELU, bool OUT_HALF>
__global__ void __launch_bounds__(256) agg_h(
    const __half* __restrict__ x, const int* __restrict__ rowptr,
    const int* __restrict__ col,
    const float* __restrict__ inv_dst, const float* __restrict__ bias,
    const float* __restrict__ prescale,  // used only when OUT_HALF
    void* __restrict__ out_, int n) {
    int r = blockIdx.x * 8 + (int)(threadIdx.x >> 5);
    if (r >= n) return;
    int lane = threadIdx.x & 31;
    int s = rowptr[r], e = rowptr[r + 1];
    float a0 = 0.f, a1 = 0.f, a2 = 0.f, a3 = 0.f;
    int i = s;
    for (; i + 4 <= e; i += 4) {
        int c0 = col[i], c1 = col[i + 1], c2 = col[i + 2], c3 = col[i + 3];
        uint2 v0 = *reinterpret_cast<const uint2*>(x + c0 * 128 + lane * 4);
        uint2 v1 = *reinterpret_cast<const uint2*>(x + c1 * 128 + lane * 4);
        uint2 v2 = *reinterpret_cast<const uint2*>(x + c2 * 128 + lane * 4);
        uint2 v3 = *reinterpret_cast<const uint2*>(x + c3 * 128 + lane * 4);
        acc4h(a0, a1, a2, a3, v0);
        acc4h(a0, a1, a2, a3, v1);
        acc4h(a0, a1, a2, a3, v2);
        acc4h(a0, a1, a2, a3, v3);
    }
    for (; i < e; i++) {
        int c0 = col[i];
        uint2 v0 = *reinterpret_cast<const uint2*>(x + c0 * 128 + lane * 4);
        acc4h(a0, a1, a2, a3, v0);
    }
    float sc = inv_dst[r];
    a0 *= sc; a1 *= sc; a2 *= sc; a3 *= sc;
    if (BIAS_RELU) {
        float4 bv = *reinterpret_cast<const float4*>(bias + lane * 4);
        a0 = fmaxf(a0 + bv.x, 0.f);
        a1 = fmaxf(a1 + bv.y, 0.f);
        a2 = fmaxf(a2 + bv.z, 0.f);
        a3 = fmaxf(a3 + bv.w, 0.f);
    }
    if (OUT_HALF) {
        float ps = prescale[r];  // fold next layer's inv_src into the stored table
        a0 *= ps; a1 *= ps; a2 *= ps; a3 *= ps;
        __half2 o0 = __floats2half2_rn(a0, a1);
        __half2 o1 = __floats2half2_rn(a2, a3);
        uint2 o;
        o.x = *reinterpret_cast<unsigned int*>(&o0);
        o.y = *reinterpret_cast<unsigned int*>(&o1);
        *reinterpret_cast<uint2*>((__half*)out_ + r * 128 + lane * 4) = o;
    } else {
        float4 o; o.x = a0; o.y = a1; o.z = a2; o.w = a3;
        *reinterpret_cast<float4*>((float*)out_ + r * 128 + lane * 4) = o;
    }
}

// ---------------------------------------------------------------------------
// GEMM kernel: fp32 in, fp32 or fp16 out. BM=BN=128, BK=8, 8x8 microtile, FFMA2.
// ---------------------------------------------------------------------------

template <bool ROW_SCALE, bool BIAS_RELU, bool OUT_HALF>
__global__ void __launch_bounds__(256) gemm128(
    const float* __restrict__ A, const float* __restrict__ W,
    const float* __restrict__ rscale, const float* __restrict__ bias,
    void* __restrict__ out_, int M) {
    __shared__ __align__(16) float As[8][128];
    __shared__ __align__(16) float Ws[8][128];
    int tid = threadIdx.x;
    int block_row = blockIdx.x * 128;
    int tm = (tid >> 4) << 3;
    int tn = (tid & 15) << 3;

    unsigned long long acc[8][4];
    #pragma unroll
    for (int i = 0; i < 8; i++)
        #pragma unroll
        for (int j = 0; j < 4; j++) acc[i][j] = 0ull;

    int ar = tid >> 1;
    int ap = (tid & 1) * 4;
    int wr = tid >> 5;
    int wc = (tid & 31) * 4;
    int gr_load = block_row + ar;

    float rs = 1.0f;
    if (ROW_SCALE && gr_load < M) rs = rscale[gr_load];

    for (int k0 = 0; k0 < 128; k0 += 8) {
        float4 av = make_float4(0.f, 0.f, 0.f, 0.f);
        if (gr_load < M)
            av = *reinterpret_cast<const float4*>(A + gr_load * 128 + k0 + ap);
        if (ROW_SCALE) { av.x *= rs; av.y *= rs; av.z *= rs; av.w *= rs; }
        As[ap + 0][ar] = av.x;
        As[ap + 1][ar] = av.y;
        As[ap + 2][ar] = av.z;
        As[ap + 3][ar] = av.w;
        *reinterpret_cast<float4*>(&Ws[wr][wc]) =
            *reinterpret_cast<const float4*>(W + (k0 + wr) * 128 + wc);
        __syncthreads();
        #pragma unroll
        for (int kk = 0; kk < 8; kk++) {
            ulonglong2 wA = *reinterpret_cast<ulonglong2*>(&Ws[kk][tn]);
            ulonglong2 wB = *reinterpret_cast<ulonglong2*>(&Ws[kk][tn + 4]);
            float4 a0 = *reinterpret_cast<float4*>(&As[kk][tm]);
            float4 a1 = *reinterpret_cast<float4*>(&As[kk][tm + 4]);
            float af[8] = {a0.x, a0.y, a0.z, a0.w, a1.x, a1.y, a1.z, a1.w};
            #pragma unroll
            for (int i = 0; i < 8; i++) {
                unsigned long long ai = pk2dup(af[i]);
                fma2(acc[i][0], ai, wA.x);
                fma2(acc[i][1], ai, wA.y);
                fma2(acc[i][2], ai, wB.x);
                fma2(acc[i][3], ai, wB.y);
            }
        }
        __syncthreads();
    }

    #pragma unroll
    for (int i = 0; i < 8; i++) {
        int gr = block_row + tm + i;
        if (gr >= M) continue;
        float2 p[4];
        #pragma unroll
        for (int j = 0; j < 4; j++) p[j] = upk2(acc[i][j]);
        if (BIAS_RELU) {
            #pragma unroll
            for (int j = 0; j < 4; j++) {
                p[j].x = fmaxf(p[j].x + bias[tn + j * 2 + 0], 0.f);
                p[j].y = fmaxf(p[j].y + bias[tn + j * 2 + 1], 0.f);
            }
        }
        if (OUT_HALF) {
            uint4 o;
            __half2 h0 = __floats2half2_rn(p[0].x, p[0].y);
            __half2 h1 = __floats2half2_rn(p[1].x, p[1].y);
            __half2 h2 = __floats2half2_rn(p[2].x, p[2].y);
            __half2 h3 = __floats2half2_rn(p[3].x, p[3].y);
            o.x = *reinterpret_cast<unsigned int*>(&h0);
            o.y = *reinterpret_cast<unsigned int*>(&h1);
            o.z = *reinterpret_cast<unsigned int*>(&h2);
            o.w = *reinterpret_cast<unsigned int*>(&h3);
            *reinterpret_cast<uint4*>((__half*)out_ + (size_t)gr * 128 + tn) = o;
        } else {
            float* out = (float*)out_;
            *reinterpret_cast<float4*>(out + (size_t)gr * 128 + tn) =
                make_float4(p[0].x, p[0].y, p[1].x, p[1].y);
            *reinterpret_cast<float4*>(out + (size_t)gr * 128 + tn + 4) =
                make_float4(p[2].x, p[2].y, p[3].x, p[3].y);
        }
    }
}

// ---------------------------------------------------------------------------
// Launch: setup, then two independent GCN chains on parallel streams.
// Chain A: h_p -> hd1 -> hp2 -> out_d     Chain B: h_d -> hp1 -> hd2 -> out_p
// p-side gather tables fp16 AND pre-scaled by inv_p_out.
// ---------------------------------------------------------------------------

extern "C" void kernel_launch(void* const* d_in, const int* in_sizes, int n_in,
                              void* d_out, int out_size) {
    const float* h_p   = (const float*)d_in[0];
    const float* h_d   = (const float*)d_in[1];
    const int* pd_src  = (const int*)d_in[2];
    const int* pd_dst  = (const int*)d_in[3];
    const int* dp_src  = (const int*)d_in[4];
    const int* dp_dst  = (const int*)d_in[5];
    const float* W1_pd = (const float*)d_in[6];
    const float* b1_pd = (const float*)d_in[7];
    const float* W1_dp = (const float*)d_in[8];
    const float* b1_dp = (const float*)d_in[9];
    const float* W2_pd = (const float*)d_in[10];
    const float* b2_pd = (const float*)d_in[11];
    const float* W2_dp = (const float*)d_in[12];
    const float* b2_dp = (const float*)d_in[13];
    const float* W3_pd = (const float*)d_in[14];
    const float* b3_pd = (const float*)d_in[15];
    const float* W3_dp = (const float*)d_in[16];
    const float* b3_dp = (const float*)d_in[17];

    int E  = in_sizes[2];
    int E2 = in_sizes[4];

    void* base = nullptr;
    cudaGetSymbolAddress(&base, g_mem);
    unsigned char* p = (unsigned char*)base;
    auto bump = [&](size_t bytes) -> void* {
        void* r = (void*)p;
        p += (bytes + 255) & ~(size_t)255;
        return r;
    };

    float* inv_p_out = (float*)bump((size_t)NP * 4);
    float* inv_d_in  = (float*)bump((size_t)ND * 4);
    float* inv_d_out = (float*)bump((size_t)ND * 4);
    float* inv_p_in  = (float*)bump((size_t)NP * 4);
    unsigned char* zero_base = p;
    int* cnt_p_out   = (int*)bump((size_t)NP * 4);
    int* cnt_d_in    = (int*)bump((size_t)ND * 4);
    int* cnt_d_out   = (int*)bump((size_t)ND * 4);
    int* cnt_p_in    = (int*)bump((size_t)NP * 4);
    int* cur_pd      = (int*)bump((size_t)ND * 4);
    int* cur_dp      = (int*)bump((size_t)NP * 4);
    size_t zero_bytes = (size_t)(p - zero_base);
    int* rp_pd       = (int*)bump((size_t)(ND + 1) * 4);
    int* rp_dp       = (int*)bump((size_t)(NP + 1) * 4);
    int* col_pd      = (int*)bump((size_t)EMAX * 4);
    int* col_dp      = (int*)bump((size_t)EMAX * 4);
    int* scan_pA     = (int*)bump((size_t)ND * 4);    // scan partials
    int* scan_pB     = (int*)bump((size_t)NP * 4);
    int* scan_sA     = (int*)bump(128 * 4);           // block sums
    int* scan_sB     = (int*)bump(128 * 4);
    __half* h_ph     = (__half*)bump((size_t)NP * 128 * 2);
    __half* hp1h     = (__half*)bump((size_t)NP * 128 * 2);
    __half* hp2h     = (__half*)bump((size_t)NP * 128 * 2);
    __half* gscrA    = (__half*)bump((size_t)ND * 128 * 2);
    __half* gscrB    = (__half*)bump((size_t)ND * 128 * 2);
    float* scrA      = (float*)bump((size_t)ND * 128 * 4);
    float* scrB      = (float*)bump((size_t)ND * 128 * 4);
    float* hd1       = (float*)bump((size_t)ND * 128 * 4);
    float* hd2       = (float*)bump((size_t)ND * 128 * 4);

    float* out_p = (float*)d_out;
    float* out_d = out_p + (size_t)NP * 128;

    // --- setup (origin stream) ---
    cudaMemsetAsync(zero_base, 0, zero_bytes);

    int Emax = (E > E2) ? E : E2;
    dim3 cg((Emax + 255) / 256, 4);
    count4<<<cg, 256>>>(pd_src, pd_dst, dp_src, dp_dst,
                        cnt_p_out, cnt_d_in, cnt_d_out, cnt_p_in, E, E, E2, E2);

    dim3 ig((NP + 255) / 256, 4);
    inv4<<<ig, 256>>>(cnt_p_out, cnt_d_in, cnt_d_out, cnt_p_in,
                      inv_p_out, inv_d_in, inv_d_out, inv_p_in, NP, ND, ND, NP);

    f2h_scaled<<<(NP * 128 / 4 + 255) / 256, 256>>>(h_p, h_ph, inv_p_out, NP * 128 / 4);

    const int SBA = (ND + 1023) / 1024;   // 49 blocks for d-side counts
    const int SBB = (NP + 1023) / 1024;   // 98 blocks for p-side counts
    dim3 sg(SBB, 2);
    scan_up<<<sg, 1024>>>(cnt_d_in, scan_pA, scan_sA, ND,
                          cnt_p_in, scan_pB, scan_sB, NP);
    scan_mid<<<2, 128>>>(scan_sA, SBA, scan_sB, SBB);
    scan_down<<<sg, 1024>>>(scan_pA, scan_sA, rp_pd, ND,
                            scan_pB, scan_sB, rp_dp, NP);

    dim3 fg((Emax + 255) / 256, 2);
    fill2<<<fg, 256>>>(pd_src, pd_dst, rp_pd, cur_pd, col_pd, E,
                       dp_src, dp_dst, rp_dp, cur_dp, col_dp, E2);

    const int AGG_D_GRID = (ND + 7) / 8;
    const int AGG_P_GRID = (NP + 7) / 8;
    const int GEMM_D_GRID = (ND + 127) / 128;

    // --- fork second stream for chain B ---
    cudaStream_t s2;
    cudaEvent_t evFork, evJoin;
    cudaStreamCreateWithFlags(&s2, cudaStreamNonBlocking);
    cudaEventCreateWithFlags(&evFork, cudaEventDisableTiming);
    cudaEventCreateWithFlags(&evJoin, cudaEventDisableTiming);
    cudaEventRecord(evFork, 0);
    cudaStreamWaitEvent(s2, evFork, 0);

    // pd: agg(prescaled half table) -> scr fp32; gemm+bias+relu -> o
    auto pd_step = [&](cudaStream_t st, float* scr, const __half* xin,
                       const float* W, const float* b, void* o) {
        agg_h<false, false><<<AGG_D_GRID, 256, 0, st>>>(
            xin, rp_pd, col_pd, inv_d_in, nullptr, nullptr, scr, ND);
        gemm128<false, true, false><<<GEMM_D_GRID, 256, 0, st>>>(
            scr, W, nullptr, b, o, ND);
    };
    // dp: gemm(fp32 x, rscale=inv_d_out) -> gscr half; agg+bias+relu -> o
    auto dp_step = [&](cudaStream_t st, __half* gscr, const float* xin,
                       const float* W, const float* b, void* o, bool ohalf) {
        gemm128<true, false, true><<<GEMM_D_GRID, 256, 0, st>>>(
            xin, W, inv_d_out, nullptr, gscr, ND);
        if (ohalf)
            agg_h<true, true><<<AGG_P_GRID, 256, 0, st>>>(
                gscr, rp_dp, col_dp, inv_p_in, b, inv_p_out, o, NP);
        else
            agg_h<true, false><<<AGG_P_GRID, 256, 0, st>>>(
                gscr, rp_dp, col_dp, inv_p_in, b, nullptr, o, NP);
    };

    // Chain A (origin stream): h_p -> hd1 -> hp2 -> out_d
    pd_step((cudaStream_t)0, scrA, h_ph, W1_pd, b1_pd, hd1);
    dp_step((cudaStream_t)0, gscrA, hd1, W2_dp, b2_dp, hp2h, true);
    pd_step((cudaStream_t)0, scrA, hp2h, W3_pd, b3_pd, out_d);

    // Chain B (s2): h_d -> hp1 -> hd2 -> out_p
    dp_step(s2, gscrB, h_d, W1_dp, b1_dp, hp1h, true);
    pd_step(s2, scrB, hp1h, W2_pd, b2_pd, hd2);
    dp_step(s2, gscrB, hd2, W3_dp, b3_dp, out_p, false);

    // --- join ---
    cudaEventRecord(evJoin, s2);
    cudaStreamWaitEvent((cudaStream_t)0, evJoin, 0);
}

// round 15
// speedup vs baseline: 2.3550x; 1.0042x over previous
#include <cuda_runtime.h>
#include <cuda_fp16.h>

#define NP 100000
#define ND 50000
#define EMAX 600000

static const size_t TOTAL_BYTES = 256ull * 1024 * 1024;
__device__ __align__(256) unsigned char g_mem[TOTAL_BYTES];

// ---------------------------------------------------------------------------
// f32x2 helpers
// ---------------------------------------------------------------------------

__device__ __forceinline__ unsigned long long pk2dup(float x) {
    unsigned long long r;
    asm("mov.b64 %0, {%1, %1};" : "=l"(r) : "f"(x));
    return r;
}
__device__ __forceinline__ void fma2(unsigned long long& d, unsigned long long a,
                                     unsigned long long b) {
    asm("fma.rn.f32x2 %0, %1, %2, %0;" : "+l"(d) : "l"(a), "l"(b));
}
__device__ __forceinline__ float2 upk2(unsigned long long v) {
    float2 f;
    asm("mov.b64 {%0, %1}, %2;" : "=f"(f.x), "=f"(f.y) : "l"(v));
    return f;
}

// ---------------------------------------------------------------------------
// Setup kernels (per-side variants for dual-stream setup)
// ---------------------------------------------------------------------------

__global__ void count2(const int* __restrict__ i0, const int* __restrict__ i1,
                       int* __restrict__ c0, int* __restrict__ c1, int E) {
    int e = blockIdx.x * blockDim.x + threadIdx.x;
    const int* idx = blockIdx.y ? i1 : i0;
    int* cnt = blockIdx.y ? c1 : c0;
    if (e < E) atomicAdd(&cnt[idx[e]], 1);
}

__global__ void inv2(const int* __restrict__ c0, const int* __restrict__ c1,
                     float* __restrict__ v0, float* __restrict__ v1,
                     int n0, int n1) {
    int i = blockIdx.x * blockDim.x + threadIdx.x;
    const int* cnt = blockIdx.y ? c1 : c0;
    float* inv = blockIdx.y ? v1 : v0;
    int n = blockIdx.y ? n1 : n0;
    if (i < n) {
        int c = cnt[i];
        if (c < 1) c = 1;
        inv[i] = rsqrtf((float)c);
    }
}

// --- 3-phase parallel scan, single-array variants ---

__global__ void scan_up1(const int* __restrict__ cnt, int* __restrict__ part,
                         int* __restrict__ sums, int n) {
    __shared__ int ws[32];
    int lane = threadIdx.x & 31;
    int warp = threadIdx.x >> 5;
    int i = blockIdx.x * 1024 + (int)threadIdx.x;
    int v = (i < n) ? cnt[i] : 0;
    int x = v;
    #pragma unroll
    for (int off = 1; off < 32; off <<= 1) {
        int y = __shfl_up_sync(0xffffffffu, x, off);
        if (lane >= off) x += y;
    }
    if (lane == 31) ws[warp] = x;
    __syncthreads();
    if (warp == 0) {
        int s = ws[lane];
        #pragma unroll
        for (int off = 1; off < 32; off <<= 1) {
            int y = __shfl_up_sync(0xffffffffu, s, off);
            if (lane >= off) s += y;
        }
        ws[lane] = s;
    }
    __syncthreads();
    int incl = x + (warp ? ws[warp - 1] : 0);
    if (i < n) part[i] = incl;
    if (threadIdx.x == 1023) sums[blockIdx.x] = incl;
}

__global__ void scan_mid1(int* __restrict__ s, int n) {
    __shared__ int ws[4];
    int lane = threadIdx.x & 31;
    int warp = threadIdx.x >> 5;
    int v = ((int)threadIdx.x < n) ? s[threadIdx.x] : 0;
    int x = v;
    #pragma unroll
    for (int off = 1; off < 32; off <<= 1) {
        int y = __shfl_up_sync(0xffffffffu, x, off);
        if (lane >= off) x += y;
    }
    if (lane == 31) ws[warp] = x;
    __syncthreads();
    int add = 0;
    for (int w = 0; w < warp; w++) add += ws[w];
    int excl = x + add - v;
    if ((int)threadIdx.x < n) s[threadIdx.x] = excl;
}

__global__ void scan_down1(const int* __restrict__ part, const int* __restrict__ sums,
                           int* __restrict__ rowptr, int n) {
    int i = blockIdx.x * 1024 + (int)threadIdx.x;
    if (i < n) rowptr[i + 1] = part[i] + sums[blockIdx.x];
    if (i == 0) rowptr[0] = 0;
}

__global__ void fill1(const int* __restrict__ src, const int* __restrict__ dst,
                      const int* __restrict__ rowptr, int* __restrict__ cursor,
                      int* __restrict__ col, int E) {
    int e = blockIdx.x * blockDim.x + threadIdx.x;
    if (e >= E) return;
    int d = dst[e];
    int pos = atomicAdd(&cursor[d], 1);
    col[rowptr[d] + pos] = src[e];
}

// fp32 -> fp16 convert with per-row pre-scale by inv_p_out.
__global__ void f2h_scaled(const float* __restrict__ in, __half* __restrict__ out,
                           const float* __restrict__ rscale, int n) {
    int i = blockIdx.x * blockDim.x + threadIdx.x;
    if (i < n) {
        float s = rscale[i >> 5];
        float4 v = reinterpret_cast<const float4*>(in)[i];
        __half2 h0 = __floats2half2_rn(v.x * s, v.y * s);
        __half2 h1 = __floats2half2_rn(v.z * s, v.w * s);
        uint2 o;
        o.x = *reinterpret_cast<unsigned int*>(&h0);
        o.y = *reinterpret_cast<unsigned int*>(&h1);
        reinterpret_cast<uint2*>(out)[i] = o;
    }
}

// ---------------------------------------------------------------------------
// Aggregation: fp16 pre-scaled gather tables, fp32 accumulation, unroll 8.
// 32 threads/row (4 features/lane via uint2), 8 rows/block.
// ---------------------------------------------------------------------------

__device__ __forceinline__ void acc4h(float& a0, float& a1, float& a2, float& a3,
                                      uint2 v) {
    __half2 h0 = *reinterpret_cast<__half2*>(&v.x);
    __half2 h1 = *reinterpret_cast<__half2*>(&v.y);
    float2 f0 = __half22float2(h0);
    float2 f1 = __half22float2(h1);
    a0 += f0.x; a1 += f0.y; a2 += f1.x; a3 += f1.y;
}

template <bool BIAS_RELU, bool OUT_HALF>
__global__ void __launch_bounds__(256) agg_h(
    const __half* __restrict__ x, const int* __restrict__ rowptr,
    const int* __restrict__ col,
    const float* __restrict__ inv_dst, const float* __restrict__ bias,
    const float* __restrict__ prescale,
    void* __restrict__ out_, int n) {
    int r = blockIdx.x * 8 + (int)(threadIdx.x >> 5);
    if (r >= n) return;
    int lane = threadIdx.x & 31;
    int s = rowptr[r], e = rowptr[r + 1];
    float a0 = 0.f, a1 = 0.f, a2 = 0.f, a3 = 0.f;
    int i = s;
    for (; i + 8 <= e; i += 8) {
        uint2 v[8];
        #pragma unroll
        for (int j = 0; j < 8; j++) {
            int c = col[i + j];
            v[j] = *reinterpret_cast<const uint2*>(x + c * 128 + lane * 4);
        }
        #pragma unroll
        for (int j = 0; j < 8; j++) acc4h(a0, a1, a2, a3, v[j]);
    }
    for (; i + 4 <= e; i += 4) {
        uint2 v[4];
        #pragma unroll
        for (int j = 0; j < 4; j++) {
            int c = col[i + j];
            v[j] = *reinterpret_cast<const uint2*>(x + c * 128 + lane * 4);
        }
        #pragma unroll
        for (int j = 0; j < 4; j++) acc4h(a0, a1, a2, a3, v[j]);
    }
    for (; i < e; i++) {
        int c0 = col[i];
        uint2 v0 = *reinterpret_cast<const uint2*>(x + c0 * 128 + lane * 4);
        acc4h(a0, a1, a2, a3, v0);
    }
    float sc = inv_dst[r];
    a0 *= sc; a1 *= sc; a2 *= sc; a3 *= sc;
    if (BIAS_RELU) {
        float4 bv = *reinterpret_cast<const float4*>(bias + lane * 4);
        a0 = fmaxf(a0 + bv.x, 0.f);
        a1 = fmaxf(a1 + bv.y, 0.f);
        a2 = fmaxf(a2 + bv.z, 0.f);
        a3 = fmaxf(a3 + bv.w, 0.f);
    }
    if (OUT_HALF) {
        float ps = prescale[r];
        a0 *= ps; a1 *= ps; a2 *= ps; a3 *= ps;
        __half2 o0 = __floats2half2_rn(a0, a1);
        __half2 o1 = __floats2half2_rn(a2, a3);
        uint2 o;
        o.x = *reinterpret_cast<unsigned int*>(&o0);
        o.y = *reinterpret_cast<unsigned int*>(&o1);
        *reinterpret_cast<uint2*>((__half*)out_ + r * 128 + lane * 4) = o;
    } else {
        float4 o; o.x = a0; o.y = a1; o.z = a2; o.w = a3;
        *reinterpret_cast<float4*>((float*)out_ + r * 128 + lane * 4) = o;
    }
}

// ---------------------------------------------------------------------------
// GEMM kernel: fp32 in, fp32 or fp16 out. BM=BN=128, BK=8, 8x8 microtile, FFMA2.
// ---------------------------------------------------------------------------

template <bool ROW_SCALE, bool BIAS_RELU, bool OUT_HALF>
__global__ void __launch_bounds__(256) gemm128(
    const float* __restrict__ A, const float* __restrict__ W,
    const float* __restrict__ rscale, const float* __restrict__ bias,
    void* __restrict__ out_, int M) {
    __shared__ __align__(16) float As[8][128];
    __shared__ __align__(16) float Ws[8][128];
    int tid = threadIdx.x;
    int block_row = blockIdx.x * 128;
    int tm = (tid >> 4) << 3;
    int tn = (tid & 15) << 3;

    unsigned long long acc[8][4];
    #pragma unroll
    for (int i = 0; i < 8; i++)
        #pragma unroll
        for (int j = 0; j < 4; j++) acc[i][j] = 0ull;

    int ar = tid >> 1;
    int ap = (tid & 1) * 4;
    int wr = tid >> 5;
    int wc = (tid & 31) * 4;
    int gr_load = block_row + ar;

    float rs = 1.0f;
    if (ROW_SCALE && gr_load < M) rs = rscale[gr_load];

    for (int k0 = 0; k0 < 128; k0 += 8) {
        float4 av = make_float4(0.f, 0.f, 0.f, 0.f);
        if (gr_load < M)
            av = *reinterpret_cast<const float4*>(A + gr_load * 128 + k0 + ap);
        if (ROW_SCALE) { av.x *= rs; av.y *= rs; av.z *= rs; av.w *= rs; }
        As[ap + 0][ar] = av.x;
        As[ap + 1][ar] = av.y;
        As[ap + 2][ar] = av.z;
        As[ap + 3][ar] = av.w;
        *reinterpret_cast<float4*>(&Ws[wr][wc]) =
            *reinterpret_cast<const float4*>(W + (k0 + wr) * 128 + wc);
        __syncthreads();
        #pragma unroll
        for (int kk = 0; kk < 8; kk++) {
            ulonglong2 wA = *reinterpret_cast<ulonglong2*>(&Ws[kk][tn]);
            ulonglong2 wB = *reinterpret_cast<ulonglong2*>(&Ws[kk][tn + 4]);
            float4 a0 = *reinterpret_cast<float4*>(&As[kk][tm]);
            float4 a1 = *reinterpret_cast<float4*>(&As[kk][tm + 4]);
            float af[8] = {a0.x, a0.y, a0.z, a0.w, a1.x, a1.y, a1.z, a1.w};
            #pragma unroll
            for (int i = 0; i < 8; i++) {
                unsigned long long ai = pk2dup(af[i]);
                fma2(acc[i][0], ai, wA.x);
                fma2(acc[i][1], ai, wA.y);
                fma2(acc[i][2], ai, wB.x);
                fma2(acc[i][3], ai, wB.y);
            }
        }
        __syncthreads();
    }

    #pragma unroll
    for (int i = 0; i < 8; i++) {
        int gr = block_row + tm + i;
        if (gr >= M) continue;
        float2 p[4];
        #pragma unroll
        for (int j = 0; j < 4; j++) p[j] = upk2(acc[i][j]);
        if (BIAS_RELU) {
            #pragma unroll
            for (int j = 0; j < 4; j++) {
                p[j].x = fmaxf(p[j].x + bias[tn + j * 2 + 0], 0.f);
                p[j].y = fmaxf(p[j].y + bias[tn + j * 2 + 1], 0.f);
            }
        }
        if (OUT_HALF) {
            uint4 o;
            __half2 h0 = __floats2half2_rn(p[0].x, p[0].y);
            __half2 h1 = __floats2half2_rn(p[1].x, p[1].y);
            __half2 h2 = __floats2half2_rn(p[2].x, p[2].y);
            __half2 h3 = __floats2half2_rn(p[3].x, p[3].y);
            o.x = *reinterpret_cast<unsigned int*>(&h0);
            o.y = *reinterpret_cast<unsigned int*>(&h1);
            o.z = *reinterpret_cast<unsigned int*>(&h2);
            o.w = *reinterpret_cast<unsigned int*>(&h3);
            *reinterpret_cast<uint4*>((__half*)out_ + (size_t)gr * 128 + tn) = o;
        } else {
            float* out = (float*)out_;
            *reinterpret_cast<float4*>(out + (size_t)gr * 128 + tn) =
                make_float4(p[0].x, p[0].y, p[1].x, p[1].y);
            *reinterpret_cast<float4*>(out + (size_t)gr * 128 + tn + 4) =
                make_float4(p[2].x, p[2].y, p[3].x, p[3].y);
        }
    }
}

// ---------------------------------------------------------------------------
// Launch: fully dual-stream — setup AND chains overlapped per side.
// Side/Chain A (s0): pd CSR + f2h; chain h_p -> hd1 -> hp2 -> out_d
// Side/Chain B (s2): dp CSR; gemm_B1 hoisted early; chain h_d -> hp1 -> hd2 -> out_p
// ---------------------------------------------------------------------------

extern "C" void kernel_launch(void* const* d_in, const int* in_sizes, int n_in,
                              void* d_out, int out_size) {
    const float* h_p   = (const float*)d_in[0];
    const float* h_d   = (const float*)d_in[1];
    const int* pd_src  = (const int*)d_in[2];
    const int* pd_dst  = (const int*)d_in[3];
    const int* dp_src  = (const int*)d_in[4];
    const int* dp_dst  = (const int*)d_in[5];
    const float* W1_pd = (const float*)d_in[6];
    const float* b1_pd = (const float*)d_in[7];
    const float* W1_dp = (const float*)d_in[8];
    const float* b1_dp = (const float*)d_in[9];
    const float* W2_pd = (const float*)d_in[10];
    const float* b2_pd = (const float*)d_in[11];
    const float* W2_dp = (const float*)d_in[12];
    const float* b2_dp = (const float*)d_in[13];
    const float* W3_pd = (const float*)d_in[14];
    const float* b3_pd = (const float*)d_in[15];
    const float* W3_dp = (const float*)d_in[16];
    const float* b3_dp = (const float*)d_in[17];

    int E  = in_sizes[2];
    int E2 = in_sizes[4];

    void* base = nullptr;
    cudaGetSymbolAddress(&base, g_mem);
    unsigned char* p = (unsigned char*)base;
    auto bump = [&](size_t bytes) -> void* {
        void* r = (void*)p;
        p += (bytes + 255) & ~(size_t)255;
        return r;
    };

    float* inv_p_out = (float*)bump((size_t)NP * 4);
    float* inv_d_in  = (float*)bump((size_t)ND * 4);
    float* inv_d_out = (float*)bump((size_t)ND * 4);
    float* inv_p_in  = (float*)bump((size_t)NP * 4);
    // side-A zero block: pd counts + cursor
    unsigned char* zeroA = p;
    int* cnt_p_out   = (int*)bump((size_t)NP * 4);
    int* cnt_d_in    = (int*)bump((size_t)ND * 4);
    int* cur_pd      = (int*)bump((size_t)ND * 4);
    size_t zeroA_bytes = (size_t)(p - zeroA);
    // side-B zero block: dp counts + cursor
    unsigned char* zeroB = p;
    int* cnt_d_out   = (int*)bump((size_t)ND * 4);
    int* cnt_p_in    = (int*)bump((size_t)NP * 4);
    int* cur_dp      = (int*)bump((size_t)NP * 4);
    size_t zeroB_bytes = (size_t)(p - zeroB);
    int* rp_pd       = (int*)bump((size_t)(ND + 1) * 4);
    int* rp_dp       = (int*)bump((size_t)(NP + 1) * 4);
    int* col_pd      = (int*)bump((size_t)EMAX * 4);
    int* col_dp      = (int*)bump((size_t)EMAX * 4);
    int* scan_pA     = (int*)bump((size_t)ND * 4);
    int* scan_pB     = (int*)bump((size_t)NP * 4);
    int* scan_sA     = (int*)bump(128 * 4);
    int* scan_sB     = (int*)bump(128 * 4);
    __half* h_ph     = (__half*)bump((size_t)NP * 128 * 2);
    __half* hp1h     = (__half*)bump((size_t)NP * 128 * 2);
    __half* hp2h     = (__half*)bump((size_t)NP * 128 * 2);
    __half* gscrA    = (__half*)bump((size_t)ND * 128 * 2);
    __half* gscrB    = (__half*)bump((size_t)ND * 128 * 2);
    float* scrA      = (float*)bump((size_t)ND * 128 * 4);
    float* scrB      = (float*)bump((size_t)ND * 128 * 4);
    float* hd1       = (float*)bump((size_t)ND * 128 * 4);
    float* hd2       = (float*)bump((size_t)ND * 128 * 4);

    float* out_p = (float*)d_out;
    float* out_d = out_p + (size_t)NP * 128;

    const int AGG_D_GRID = (ND + 7) / 8;
    const int AGG_P_GRID = (NP + 7) / 8;
    const int GEMM_D_GRID = (ND + 127) / 128;
    const int SBA = (ND + 1023) / 1024;
    const int SBB = (NP + 1023) / 1024;

    // --- fork s2 immediately ---
    cudaStream_t s2;
    cudaEvent_t evFork, evInvA, evFillA, evFillB, evJoin;
    cudaStreamCreateWithFlags(&s2, cudaStreamNonBlocking);
    cudaEventCreateWithFlags(&evFork, cudaEventDisableTiming);
    cudaEventCreateWithFlags(&evInvA, cudaEventDisableTiming);
    cudaEventCreateWithFlags(&evFillA, cudaEventDisableTiming);
    cudaEventCreateWithFlags(&evFillB, cudaEventDisableTiming);
    cudaEventCreateWithFlags(&evJoin, cudaEventDisableTiming);

    cudaMemsetAsync(zeroA, 0, zeroA_bytes, (cudaStream_t)0);
    cudaEventRecord(evFork, 0);
    cudaStreamWaitEvent(s2, evFork, 0);
    cudaMemsetAsync(zeroB, 0, zeroB_bytes, s2);

    // Side B setup on s2 (submitted first so gemm_B1 is the 4th kernel launch)
    dim3 cgB((E2 + 255) / 256, 2);
    count2<<<cgB, 256, 0, s2>>>(dp_src, dp_dst, cnt_d_out, cnt_p_in, E2);   // #1
    dim3 igB((NP + 255) / 256, 2);
    inv2<<<igB, 256, 0, s2>>>(cnt_d_out, cnt_p_in, inv_d_out, inv_p_in, ND, NP); // #2

    // Side A setup begins on s0
    dim3 cgA((E + 255) / 256, 2);
    count2<<<cgA, 256, 0, (cudaStream_t)0>>>(pd_src, pd_dst, cnt_p_out, cnt_d_in, E); // #3

    // Hoisted chain-B first GEMM (needs only inv_d_out + h_d)  — profiled launch #4
    gemm128<true, false, true><<<GEMM_D_GRID, 256, 0, s2>>>(
        h_d, W1_dp, inv_d_out, nullptr, gscrB, ND);                          // #4

    dim3 igA((NP + 255) / 256, 2);
    inv2<<<igA, 256, 0, (cudaStream_t)0>>>(cnt_p_out, cnt_d_in, inv_p_out, inv_d_in, NP, ND);
    cudaEventRecord(evInvA, 0);
    f2h_scaled<<<(NP * 128 / 4 + 255) / 256, 256, 0, (cudaStream_t)0>>>(
        h_p, h_ph, inv_p_out, NP * 128 / 4);

    // Side B CSR on s2
    scan_up1<<<SBB, 1024, 0, s2>>>(cnt_p_in, scan_pB, scan_sB, NP);
    scan_mid1<<<1, 128, 0, s2>>>(scan_sB, SBB);
    scan_down1<<<SBB, 1024, 0, s2>>>(scan_pB, scan_sB, rp_dp, NP);
    fill1<<<(E2 + 255) / 256, 256, 0, s2>>>(dp_src, dp_dst, rp_dp, cur_dp, col_dp, E2);
    cudaEventRecord(evFillB, s2);

    // Side A CSR on s0
    scan_up1<<<SBA, 1024, 0, (cudaStream_t)0>>>(cnt_d_in, scan_pA, scan_sA, ND);
    scan_mid1<<<1, 128, 0, (cudaStream_t)0>>>(scan_sA, SBA);
    scan_down1<<<SBA, 1024, 0, (cudaStream_t)0>>>(scan_pA, scan_sA, rp_pd, ND);
    fill1<<<(E + 255) / 256, 256, 0, (cudaStream_t)0>>>(pd_src, pd_dst, rp_pd, cur_pd, col_pd, E);
    cudaEventRecord(evFillA, 0);

    // ---- Chain A on s0: h_p -> hd1 -> hp2 -> out_d ----
    // A1 (pd): agg + gemm
    agg_h<false, false><<<AGG_D_GRID, 256, 0, (cudaStream_t)0>>>(
        h_ph, rp_pd, col_pd, inv_d_in, nullptr, nullptr, scrA, ND);
    gemm128<false, true, false><<<GEMM_D_GRID, 256, 0, (cudaStream_t)0>>>(
        scrA, W1_pd, nullptr, b1_pd, hd1, ND);
    // A2 (dp): needs dp CSR from side B
    cudaStreamWaitEvent((cudaStream_t)0, evFillB, 0);
    gemm128<true, false, true><<<GEMM_D_GRID, 256, 0, (cudaStream_t)0>>>(
        hd1, W2_dp, inv_d_out, nullptr, gscrA, ND);
    agg_h<true, true><<<AGG_P_GRID, 256, 0, (cudaStream_t)0>>>(
        gscrA, rp_dp, col_dp, inv_p_in, b2_dp, inv_p_out, hp2h, NP);
    // A3 (pd)
    agg_h<false, false><<<AGG_D_GRID, 256, 0, (cudaStream_t)0>>>(
        hp2h, rp_pd, col_pd, inv_d_in, nullptr, nullptr, scrA, ND);
    gemm128<false, true, false><<<GEMM_D_GRID, 256, 0, (cudaStream_t)0>>>(
        scrA, W3_pd, nullptr, b3_pd, out_d, ND);

    // ---- Chain B on s2: h_d -> hp1 -> hd2 -> out_p ----
    // B1 agg (gemm already done): needs inv_p_out from side A
    cudaStreamWaitEvent(s2, evInvA, 0);
    agg_h<true, true><<<AGG_P_GRID, 256, 0, s2>>>(
        gscrB, rp_dp, col_dp, inv_p_in, b1_dp, inv_p_out, hp1h, NP);
    // B2 (pd): needs pd CSR from side A
    cudaStreamWaitEvent(s2, evFillA, 0);
    agg_h<false, false><<<AGG_D_GRID, 256, 0, s2>>>(
        hp1h, rp_pd, col_pd, inv_d_in, nullptr, nullptr, scrB, ND);
    gemm128<false, true, false><<<GEMM_D_GRID, 256, 0, s2>>>(
        scrB, W2_pd, nullptr, b2_pd, hd2, ND);
    // B3 (dp)
    gemm128<true, false, true><<<GEMM_D_GRID, 256, 0, s2>>>(
        hd2, W3_dp, inv_d_out, nullptr, gscrB, ND);
    agg_h<true, false><<<AGG_P_GRID, 256, 0, s2>>>(
        gscrB, rp_dp, col_dp, inv_p_in, b3_dp, nullptr, out_p, NP);

    // --- join ---
    cudaEventRecord(evJoin, s2);
    cudaStreamWaitEvent((cudaStream_t)0, evJoin, 0);
}

// round 17
// speedup vs baseline: 2.3842x; 1.0124x over previous
#include <cuda_runtime.h>
#include <cuda_fp16.h>

#define NP 100000
#define ND 50000
#define EMAX 600000

static const size_t TOTAL_BYTES = 256ull * 1024 * 1024;
__device__ __align__(256) unsigned char g_mem[TOTAL_BYTES];

// ---------------------------------------------------------------------------
// f32x2 helpers
// ---------------------------------------------------------------------------

__device__ __forceinline__ unsigned long long pk2dup(float x) {
    unsigned long long r;
    asm("mov.b64 %0, {%1, %1};" : "=l"(r) : "f"(x));
    return r;
}
__device__ __forceinline__ void fma2(unsigned long long& d, unsigned long long a,
                                     unsigned long long b) {
    asm("fma.rn.f32x2 %0, %1, %2, %0;" : "+l"(d) : "l"(a), "l"(b));
}
__device__ __forceinline__ float2 upk2(unsigned long long v) {
    float2 f;
    asm("mov.b64 {%0, %1}, %2;" : "=f"(f.x), "=f"(f.y) : "l"(v));
    return f;
}

// ---------------------------------------------------------------------------
// Setup kernels
// ---------------------------------------------------------------------------

__global__ void count2(const int* __restrict__ i0, const int* __restrict__ i1,
                       int* __restrict__ c0, int* __restrict__ c1, int E) {
    int e = blockIdx.x * blockDim.x + threadIdx.x;
    const int* idx = blockIdx.y ? i1 : i0;
    int* cnt = blockIdx.y ? c1 : c0;
    if (e < E) atomicAdd(&cnt[idx[e]], 1);
}

__global__ void inv2(const int* __restrict__ c0, const int* __restrict__ c1,
                     float* __restrict__ v0, float* __restrict__ v1,
                     int n0, int n1) {
    int i = blockIdx.x * blockDim.x + threadIdx.x;
    const int* cnt = blockIdx.y ? c1 : c0;
    float* inv = blockIdx.y ? v1 : v0;
    int n = blockIdx.y ? n1 : n0;
    if (i < n) {
        int c = cnt[i];
        if (c < 1) c = 1;
        inv[i] = rsqrtf((float)c);
    }
}

__global__ void scan_up1(const int* __restrict__ cnt, int* __restrict__ part,
                         int* __restrict__ sums, int n) {
    __shared__ int ws[32];
    int lane = threadIdx.x & 31;
    int warp = threadIdx.x >> 5;
    int i = blockIdx.x * 1024 + (int)threadIdx.x;
    int v = (i < n) ? cnt[i] : 0;
    int x = v;
    #pragma unroll
    for (int off = 1; off < 32; off <<= 1) {
        int y = __shfl_up_sync(0xffffffffu, x, off);
        if (lane >= off) x += y;
    }
    if (lane == 31) ws[warp] = x;
    __syncthreads();
    if (warp == 0) {
        int s = ws[lane];
        #pragma unroll
        for (int off = 1; off < 32; off <<= 1) {
            int y = __shfl_up_sync(0xffffffffu, s, off);
            if (lane >= off) s += y;
        }
        ws[lane] = s;
    }
    __syncthreads();
    int incl = x + (warp ? ws[warp - 1] : 0);
    if (i < n) part[i] = incl;
    if (threadIdx.x == 1023) sums[blockIdx.x] = incl;
}

__global__ void scan_mid1(int* __restrict__ s, int n) {
    __shared__ int ws[4];
    int lane = threadIdx.x & 31;
    int warp = threadIdx.x >> 5;
    int v = ((int)threadIdx.x < n) ? s[threadIdx.x] : 0;
    int x = v;
    #pragma unroll
    for (int off = 1; off < 32; off <<= 1) {
        int y = __shfl_up_sync(0xffffffffu, x, off);
        if (lane >= off) x += y;
    }
    if (lane == 31) ws[warp] = x;
    __syncthreads();
    int add = 0;
    for (int w = 0; w < warp; w++) add += ws[w];
    int excl = x + add - v;
    if ((int)threadIdx.x < n) s[threadIdx.x] = excl;
}

__global__ void scan_down1(const int* __restrict__ part, const int* __restrict__ sums,
                           int* __restrict__ rowptr, int n) {
    int i = blockIdx.x * 1024 + (int)threadIdx.x;
    if (i < n) rowptr[i + 1] = part[i] + sums[blockIdx.x];
    if (i == 0) rowptr[0] = 0;
}

__global__ void fill1(const int* __restrict__ src, const int* __restrict__ dst,
                      const int* __restrict__ rowptr, int* __restrict__ cursor,
                      int* __restrict__ col, int E) {
    int e = blockIdx.x * blockDim.x + threadIdx.x;
    if (e >= E) return;
    int d = dst[e];
    int pos = atomicAdd(&cursor[d], 1);
    col[rowptr[d] + pos] = src[e];
}

__global__ void f2h_scaled(const float* __restrict__ in, __half* __restrict__ out,
                           const float* __restrict__ rscale, int n) {
    int i = blockIdx.x * blockDim.x + threadIdx.x;
    if (i < n) {
        float s = rscale[i >> 5];
        float4 v = reinterpret_cast<const float4*>(in)[i];
        __half2 h0 = __floats2half2_rn(v.x * s, v.y * s);
        __half2 h1 = __floats2half2_rn(v.z * s, v.w * s);
        uint2 o;
        o.x = *reinterpret_cast<unsigned int*>(&h0);
        o.y = *reinterpret_cast<unsigned int*>(&h1);
        reinterpret_cast<uint2*>(out)[i] = o;
    }
}

// ---------------------------------------------------------------------------
// Aggregation (unchanged from R15)
// ---------------------------------------------------------------------------

__device__ __forceinline__ void acc4h(float& a0, float& a1, float& a2, float& a3,
                                      uint2 v) {
    __half2 h0 = *reinterpret_cast<__half2*>(&v.x);
    __half2 h1 = *reinterpret_cast<__half2*>(&v.y);
    float2 f0 = __half22float2(h0);
    float2 f1 = __half22float2(h1);
    a0 += f0.x; a1 += f0.y; a2 += f1.x; a3 += f1.y;
}

template <bool BIAS_RELU, bool OUT_HALF>
__global__ void __launch_bounds__(256) agg_h(
    const __half* __restrict__ x, const int* __restrict__ rowptr,
    const int* __restrict__ col,
    const float* __restrict__ inv_dst, const float* __restrict__ bias,
    const float* __restrict__ prescale,
    void* __restrict__ out_, int n) {
    int r = blockIdx.x * 8 + (int)(threadIdx.x >> 5);
    if (r >= n) return;
    int lane = threadIdx.x & 31;
    int s = rowptr[r], e = rowptr[r + 1];
    float a0 = 0.f, a1 = 0.f, a2 = 0.f, a3 = 0.f;
    int i = s;
    for (; i + 8 <= e; i += 8) {
        uint2 v[8];
        #pragma unroll
        for (int j = 0; j < 8; j++) {
            int c = col[i + j];
            v[j] = *reinterpret_cast<const uint2*>(x + c * 128 + lane * 4);
        }
        #pragma unroll
        for (int j = 0; j < 8; j++) acc4h(a0, a1, a2, a3, v[j]);
    }
    for (; i + 4 <= e; i += 4) {
        uint2 v[4];
        #pragma unroll
        for (int j = 0; j < 4; j++) {
            int c = col[i + j];
            v[j] = *reinterpret_cast<const uint2*>(x + c * 128 + lane * 4);
        }
        #pragma unroll
        for (int j = 0; j < 4; j++) acc4h(a0, a1, a2, a3, v[j]);
    }
    for (; i < e; i++) {
        int c0 = col[i];
        uint2 v0 = *reinterpret_cast<const uint2*>(x + c0 * 128 + lane * 4);
        acc4h(a0, a1, a2, a3, v0);
    }
    float sc = inv_dst[r];
    a0 *= sc; a1 *= sc; a2 *= sc; a3 *= sc;
    if (BIAS_RELU) {
        float4 bv = *reinterpret_cast<const float4*>(bias + lane * 4);
        a0 = fmaxf(a0 + bv.x, 0.f);
        a1 = fmaxf(a1 + bv.y, 0.f);
        a2 = fmaxf(a2 + bv.z, 0.f);
        a3 = fmaxf(a3 + bv.w, 0.f);
    }
    if (OUT_HALF) {
        float ps = prescale[r];
        a0 *= ps; a1 *= ps; a2 *= ps; a3 *= ps;
        __half2 o0 = __floats2half2_rn(a0, a1);
        __half2 o1 = __floats2half2_rn(a2, a3);
        uint2 o;
        o.x = *reinterpret_cast<unsigned int*>(&o0);
        o.y = *reinterpret_cast<unsigned int*>(&o1);
        *reinterpret_cast<uint2*>((__half*)out_ + r * 128 + lane * 4) = o;
    } else {
        float4 o; o.x = a0; o.y = a1; o.z = a2; o.w = a3;
        *reinterpret_cast<float4*>((float*)out_ + r * 128 + lane * 4) = o;
    }
}

// ---------------------------------------------------------------------------
// GEMM v3: BK=16, double-buffered smem, ONE barrier per k-iter (8 total),
// global loads issued before compute (latency hidden), row-scale in epilogue.
// ---------------------------------------------------------------------------

template <bool ROW_SCALE, bool BIAS_RELU, bool OUT_HALF>
__global__ void __launch_bounds__(256) gemm128(
    const float* __restrict__ A, const float* __restrict__ W,
    const float* __restrict__ rscale, const float* __restrict__ bias,
    void* __restrict__ out_, int M) {
    __shared__ __align__(16) float As[2][16][128];  // [stage][k][m]
    __shared__ __align__(16) float Ws[2][16][128];  // [stage][k][n]
    int tid = threadIdx.x;
    int block_row = blockIdx.x * 128;
    int tm = (tid >> 4) << 3;
    int tn = (tid & 15) << 3;

    unsigned long long acc[8][4];
    #pragma unroll
    for (int i = 0; i < 8; i++)
        #pragma unroll
        for (int j = 0; j < 4; j++) acc[i][j] = 0ull;

    int ar = tid >> 1;             // A row within tile
    int ap = (tid & 1) * 8;        // k offset: 0 or 8
    int wr = tid >> 5;             // W k-row 0..7 (also +8)
    int wc = (tid & 31) * 4;
    int gr = block_row + ar;
    bool valid = gr < M;
    const float* Arow = A + (size_t)gr * 128;

    // prologue: load + store stage 0
    float4 a0v = make_float4(0.f, 0.f, 0.f, 0.f), a1v = a0v;
    if (valid) {
        a0v = *reinterpret_cast<const float4*>(Arow + ap);
        a1v = *reinterpret_cast<const float4*>(Arow + ap + 4);
    }
    float4 w0v = *reinterpret_cast<const float4*>(W + wr * 128 + wc);
    float4 w1v = *reinterpret_cast<const float4*>(W + (wr + 8) * 128 + wc);
    {
        float af[8] = {a0v.x, a0v.y, a0v.z, a0v.w, a1v.x, a1v.y, a1v.z, a1v.w};
        #pragma unroll
        for (int j = 0; j < 8; j++) As[0][ap + j][ar] = af[j];
        *reinterpret_cast<float4*>(&Ws[0][wr][wc]) = w0v;
        *reinterpret_cast<float4*>(&Ws[0][wr + 8][wc]) = w1v;
    }

    #pragma unroll
    for (int it = 0; it < 8; it++) {
        __syncthreads();
        int cur = it & 1, nxt = cur ^ 1;
        float4 na0 = make_float4(0.f, 0.f, 0.f, 0.f), na1 = na0, nw0, nw1;
        if (it < 7) {
            int kb = (it + 1) * 16;
            if (valid) {
                na0 = *reinterpret_cast<const float4*>(Arow + kb + ap);
                na1 = *reinterpret_cast<const float4*>(Arow + kb + ap + 4);
            }
            nw0 = *reinterpret_cast<const float4*>(W + (kb + wr) * 128 + wc);
            nw1 = *reinterpret_cast<const float4*>(W + (kb + wr + 8) * 128 + wc);
        }
        #pragma unroll
        for (int kk = 0; kk < 16; kk++) {
            ulonglong2 wA = *reinterpret_cast<ulonglong2*>(&Ws[cur][kk][tn]);
            ulonglong2 wB = *reinterpret_cast<ulonglong2*>(&Ws[cur][kk][tn + 4]);
            float4 fa0 = *reinterpret_cast<float4*>(&As[cur][kk][tm]);
            float4 fa1 = *reinterpret_cast<float4*>(&As[cur][kk][tm + 4]);
            float af[8] = {fa0.x, fa0.y, fa0.z, fa0.w, fa1.x, fa1.y, fa1.z, fa1.w};
            #pragma unroll
            for (int i = 0; i < 8; i++) {
                unsigned long long ai = pk2dup(af[i]);
                fma2(acc[i][0], ai, wA.x);
                fma2(acc[i][1], ai, wA.y);
                fma2(acc[i][2], ai, wB.x);
                fma2(acc[i][3], ai, wB.y);
            }
        }
        if (it < 7) {
            float af[8] = {na0.x, na0.y, na0.z, na0.w, na1.x, na1.y, na1.z, na1.w};
            #pragma unroll
            for (int j = 0; j < 8; j++) As[nxt][ap + j][ar] = af[j];
            *reinterpret_cast<float4*>(&Ws[nxt][wr][wc]) = nw0;
            *reinterpret_cast<float4*>(&Ws[nxt][wr + 8][wc]) = nw1;
        }
    }

    // epilogue: row scale (moved here), bias/relu, store
    float rsw[8];
    #pragma unroll
    for (int i = 0; i < 8; i++) {
        int r = block_row + tm + i;
        rsw[i] = (ROW_SCALE && r < M) ? rscale[r] : 1.0f;
    }
    #pragma unroll
    for (int i = 0; i < 8; i++) {
        int gr2 = block_row + tm + i;
        if (gr2 >= M) continue;
        float2 p[4];
        #pragma unroll
        for (int j = 0; j < 4; j++) {
            p[j] = upk2(acc[i][j]);
            if (ROW_SCALE) { p[j].x *= rsw[i]; p[j].y *= rsw[i]; }
        }
        if (BIAS_RELU) {
            #pragma unroll
            for (int j = 0; j < 4; j++) {
                p[j].x = fmaxf(p[j].x + bias[tn + j * 2 + 0], 0.f);
                p[j].y = fmaxf(p[j].y + bias[tn + j * 2 + 1], 0.f);
            }
        }
        if (OUT_HALF) {
            uint4 o;
            __half2 h0 = __floats2half2_rn(p[0].x, p[0].y);
            __half2 h1 = __floats2half2_rn(p[1].x, p[1].y);
            __half2 h2 = __floats2half2_rn(p[2].x, p[2].y);
            __half2 h3 = __floats2half2_rn(p[3].x, p[3].y);
            o.x = *reinterpret_cast<unsigned int*>(&h0);
            o.y = *reinterpret_cast<unsigned int*>(&h1);
            o.z = *reinterpret_cast<unsigned int*>(&h2);
            o.w = *reinterpret_cast<unsigned int*>(&h3);
            *reinterpret_cast<uint4*>((__half*)out_ + (size_t)gr2 * 128 + tn) = o;
        } else {
            float* out = (float*)out_;
            *reinterpret_cast<float4*>(out + (size_t)gr2 * 128 + tn) =
                make_float4(p[0].x, p[0].y, p[1].x, p[1].y);
            *reinterpret_cast<float4*>(out + (size_t)gr2 * 128 + tn + 4) =
                make_float4(p[2].x, p[2].y, p[3].x, p[3].y);
        }
    }
}

// ---------------------------------------------------------------------------
// Launch: dual-stream setup + chains (structure unchanged from R15)
// ---------------------------------------------------------------------------

extern "C" void kernel_launch(void* const* d_in, const int* in_sizes, int n_in,
                              void* d_out, int out_size) {
    const float* h_p   = (const float*)d_in[0];
    const float* h_d   = (const float*)d_in[1];
    const int* pd_src  = (const int*)d_in[2];
    const int* pd_dst  = (const int*)d_in[3];
    const int* dp_src  = (const int*)d_in[4];
    const int* dp_dst  = (const int*)d_in[5];
    const float* W1_pd = (const float*)d_in[6];
    const float* b1_pd = (const float*)d_in[7];
    const float* W1_dp = (const float*)d_in[8];
    const float* b1_dp = (const float*)d_in[9];
    const float* W2_pd = (const float*)d_in[10];
    const float* b2_pd = (const float*)d_in[11];
    const float* W2_dp = (const float*)d_in[12];
    const float* b2_dp = (const float*)d_in[13];
    const float* W3_pd = (const float*)d_in[14];
    const float* b3_pd = (const float*)d_in[15];
    const float* W3_dp = (const float*)d_in[16];
    const float* b3_dp = (const float*)d_in[17];

    int E  = in_sizes[2];
    int E2 = in_sizes[4];

    void* base = nullptr;
    cudaGetSymbolAddress(&base, g_mem);
    unsigned char* p = (unsigned char*)base;
    auto bump = [&](size_t bytes) -> void* {
        void* r = (void*)p;
        p += (bytes + 255) & ~(size_t)255;
        return r;
    };

    float* inv_p_out = (float*)bump((size_t)NP * 4);
    float* inv_d_in  = (float*)bump((size_t)ND * 4);
    float* inv_d_out = (float*)bump((size_t)ND * 4);
    float* inv_p_in  = (float*)bump((size_t)NP * 4);
    unsigned char* zeroA = p;
    int* cnt_p_out   = (int*)bump((size_t)NP * 4);
    int* cnt_d_in    = (int*)bump((size_t)ND * 4);
    int* cur_pd      = (int*)bump((size_t)ND * 4);
    size_t zeroA_bytes = (size_t)(p - zeroA);
    unsigned char* zeroB = p;
    int* cnt_d_out   = (int*)bump((size_t)ND * 4);
    int* cnt_p_in    = (int*)bump((size_t)NP * 4);
    int* cur_dp      = (int*)bump((size_t)NP * 4);
    size_t zeroB_bytes = (size_t)(p - zeroB);
    int* rp_pd       = (int*)bump((size_t)(ND + 1) * 4);
    int* rp_dp       = (int*)bump((size_t)(NP + 1) * 4);
    int* col_pd      = (int*)bump((size_t)EMAX * 4);
    int* col_dp      = (int*)bump((size_t)EMAX * 4);
    int* scan_pA     = (int*)bump((size_t)ND * 4);
    int* scan_pB     = (int*)bump((size_t)NP * 4);
    int* scan_sA     = (int*)bump(128 * 4);
    int* scan_sB     = (int*)bump(128 * 4);
    __half* h_ph     = (__half*)bump((size_t)NP * 128 * 2);
    __half* hp1h     = (__half*)bump((size_t)NP * 128 * 2);
    __half* hp2h     = (__half*)bump((size_t)NP * 128 * 2);
    __half* gscrA    = (__half*)bump((size_t)ND * 128 * 2);
    __half* gscrB    = (__half*)bump((size_t)ND * 128 * 2);
    float* scrA      = (float*)bump((size_t)ND * 128 * 4);
    float* scrB      = (float*)bump((size_t)ND * 128 * 4);
    float* hd1       = (float*)bump((size_t)ND * 128 * 4);
    float* hd2       = (float*)bump((size_t)ND * 128 * 4);

    float* out_p = (float*)d_out;
    float* out_d = out_p + (size_t)NP * 128;

    const int AGG_D_GRID = (ND + 7) / 8;
    const int AGG_P_GRID = (NP + 7) / 8;
    const int GEMM_D_GRID = (ND + 127) / 128;
    const int SBA = (ND + 1023) / 1024;
    const int SBB = (NP + 1023) / 1024;

    cudaStream_t s2;
    cudaEvent_t evFork, evInvA, evFillA, evFillB, evJoin;
    cudaStreamCreateWithFlags(&s2, cudaStreamNonBlocking);
    cudaEventCreateWithFlags(&evFork, cudaEventDisableTiming);
    cudaEventCreateWithFlags(&evInvA, cudaEventDisableTiming);
    cudaEventCreateWithFlags(&evFillA, cudaEventDisableTiming);
    cudaEventCreateWithFlags(&evFillB, cudaEventDisableTiming);
    cudaEventCreateWithFlags(&evJoin, cudaEventDisableTiming);

    cudaMemsetAsync(zeroA, 0, zeroA_bytes, (cudaStream_t)0);
    cudaEventRecord(evFork, 0);
    cudaStreamWaitEvent(s2, evFork, 0);
    cudaMemsetAsync(zeroB, 0, zeroB_bytes, s2);

    dim3 cgB((E2 + 255) / 256, 2);
    count2<<<cgB, 256, 0, s2>>>(dp_src, dp_dst, cnt_d_out, cnt_p_in, E2);   // #1
    dim3 igB((NP + 255) / 256, 2);
    inv2<<<igB, 256, 0, s2>>>(cnt_d_out, cnt_p_in, inv_d_out, inv_p_in, ND, NP); // #2

    dim3 cgA((E + 255) / 256, 2);
    count2<<<cgA, 256, 0, (cudaStream_t)0>>>(pd_src, pd_dst, cnt_p_out, cnt_d_in, E); // #3

    // hoisted chain-B GEMM — profiled launch #4
    gemm128<true, false, true><<<GEMM_D_GRID, 256, 0, s2>>>(
        h_d, W1_dp, inv_d_out, nullptr, gscrB, ND);                          // #4

    dim3 igA((NP + 255) / 256, 2);
    inv2<<<igA, 256, 0, (cudaStream_t)0>>>(cnt_p_out, cnt_d_in, inv_p_out, inv_d_in, NP, ND);
    cudaEventRecord(evInvA, 0);
    f2h_scaled<<<(NP * 128 / 4 + 255) / 256, 256, 0, (cudaStream_t)0>>>(
        h_p, h_ph, inv_p_out, NP * 128 / 4);

    scan_up1<<<SBB, 1024, 0, s2>>>(cnt_p_in, scan_pB, scan_sB, NP);
    scan_mid1<<<1, 128, 0, s2>>>(scan_sB, SBB);
    scan_down1<<<SBB, 1024, 0, s2>>>(scan_pB, scan_sB, rp_dp, NP);
    fill1<<<(E2 + 255) / 256, 256, 0, s2>>>(dp_src, dp_dst, rp_dp, cur_dp, col_dp, E2);
    cudaEventRecord(evFillB, s2);

    scan_up1<<<SBA, 1024, 0, (cudaStream_t)0>>>(cnt_d_in, scan_pA, scan_sA, ND);
    scan_mid1<<<1, 128, 0, (cudaStream_t)0>>>(scan_sA, SBA);
    scan_down1<<<SBA, 1024, 0, (cudaStream_t)0>>>(scan_pA, scan_sA, rp_pd, ND);
    fill1<<<(E + 255) / 256, 256, 0, (cudaStream_t)0>>>(pd_src, pd_dst, rp_pd, cur_pd, col_pd, E);
    cudaEventRecord(evFillA, 0);

    // ---- Chain A on s0: h_p -> hd1 -> hp2 -> out_d ----
    agg_h<false, false><<<AGG_D_GRID, 256, 0, (cudaStream_t)0>>>(
        h_ph, rp_pd, col_pd, inv_d_in, nullptr, nullptr, scrA, ND);
    gemm128<false, true, false><<<GEMM_D_GRID, 256, 0, (cudaStream_t)0>>>(
        scrA, W1_pd, nullptr, b1_pd, hd1, ND);
    cudaStreamWaitEvent((cudaStream_t)0, evFillB, 0);
    gemm128<true, false, true><<<GEMM_D_GRID, 256, 0, (cudaStream_t)0>>>(
        hd1, W2_dp, inv_d_out, nullptr, gscrA, ND);
    agg_h<true, true><<<AGG_P_GRID, 256, 0, (cudaStream_t)0>>>(
        gscrA, rp_dp, col_dp, inv_p_in, b2_dp, inv_p_out, hp2h, NP);
    agg_h<false, false><<<AGG_D_GRID, 256, 0, (cudaStream_t)0>>>(
        hp2h, rp_pd, col_pd, inv_d_in, nullptr, nullptr, scrA, ND);
    gemm128<false, true, false><<<GEMM_D_GRID, 256, 0, (cudaStream_t)0>>>(
        scrA, W3_pd, nullptr, b3_pd, out_d, ND);

    // ---- Chain B on s2: h_d -> hp1 -> hd2 -> out_p ----
    cudaStreamWaitEvent(s2, evInvA, 0);
    agg_h<true, true><<<AGG_P_GRID, 256, 0, s2>>>(
        gscrB, rp_dp, col_dp, inv_p_in, b1_dp, inv_p_out, hp1h, NP);
    cudaStreamWaitEvent(s2, evFillA, 0);
    agg_h<false, false><<<AGG_D_GRID, 256, 0, s2>>>(
        hp1h, rp_pd, col_pd, inv_d_in, nullptr, nullptr, scrB, ND);
    gemm128<false, true, false><<<GEMM_D_GRID, 256, 0, s2>>>(
        scrB, W2_pd, nullptr, b2_pd, hd2, ND);
    gemm128<true, false, true><<<GEMM_D_GRID, 256, 0, s2>>>(
        hd2, W3_dp, inv_d_out, nullptr, gscrB, ND);
    agg_h<true, false><<<AGG_P_GRID, 256, 0, s2>>>(
        gscrB, rp_dp, col_dp, inv_p_in, b3_dp, nullptr, out_p, NP);

    cudaEventRecord(evJoin, s2);
    cudaStreamWaitEvent((cudaStream_t)0, evJoin, 0);
}